// round 6
// baseline (speedup 1.0000x reference)
#include <cuda_runtime.h>
#include <cuda_fp16.h>

#define NMAX 100000
#define EMAX 1600000

typedef unsigned long long ull;

// ---------------- device scratch ----------------
__device__ float  g_deg   [NMAX];
__device__ float  g_dinv  [NMAX];
__device__ __half g_tmp16 [NMAX * 64];   // h * dinv[src], fp16
__device__ float  g_h1    [NMAX * 64];
__device__ float  g_h2    [NMAX * 64];
__device__ float  g_logits[NMAX * 32];
__device__ float  g_wts   [NMAX];
__device__ int    g_rowptr[NMAX + 1];
__device__ int    g_fill  [NMAX];
__device__ int    g_csrc  [EMAX];
__device__ int    g_bsum  [64];
__device__ int    g_boff  [64];
__device__ int    g_mmint [2];           // int-encoded min/max of wts (all positive)
__device__ float  g_acc   [33];

// ---------------- f32x2 packed helpers ----------------
__device__ __forceinline__ ull pack2(float a, float b) {
    ull r; unsigned ia = __float_as_uint(a), ib = __float_as_uint(b);
    asm("mov.b64 %0, {%1, %2};" : "=l"(r) : "r"(ia), "r"(ib));
    return r;
}
__device__ __forceinline__ void ffma2(ull& d, ull a, ull b) {
    asm("fma.rn.f32x2 %0, %1, %2, %0;" : "+l"(d) : "l"(a), "l"(b));
}
__device__ __forceinline__ float2 unp(ull v) {
    float2 r; unsigned lo = (unsigned)v, hi = (unsigned)(v >> 32);
    r.x = __uint_as_float(lo); r.y = __uint_as_float(hi);
    return r;
}

// ---------------- degree ----------------
__global__ void deg_init_k(int n) {
    int i = blockIdx.x * blockDim.x + threadIdx.x;
    if (i < n) g_deg[i] = 1.0f;   // self-loop
}
__global__ void deg_count_k(const int* __restrict__ dstI, int e) {
    int i = blockIdx.x * blockDim.x + threadIdx.x;
    if (i < e) atomicAdd(&g_deg[dstI[i]], 1.0f);
}

// ---------------- parallel CSR rowptr scan (3 stages) ----------------
__global__ void __launch_bounds__(256) scan1_k(int n) {
    __shared__ int wsum[8];
    int t = threadIdx.x;
    int base = blockIdx.x * 2048 + t * 8;
    int d[8]; int s = 0;
#pragma unroll
    for (int i = 0; i < 8; i++) {
        int idx = base + i;
        float dg = (idx < n) ? g_deg[idx] : 1.0f;
        if (idx < n) g_dinv[idx] = rsqrtf(dg);
        d[i] = (idx < n) ? (int)dg - 1 : 0;
        s += d[i];
    }
    int lane = t & 31, w = t >> 5;
    int inc = s;
#pragma unroll
    for (int off = 1; off < 32; off <<= 1) {
        int v = __shfl_up_sync(0xffffffffu, inc, off);
        if (lane >= off) inc += v;
    }
    if (lane == 31) wsum[w] = inc;
    __syncthreads();
    if (w == 0) {
        int v = (lane < 8) ? wsum[lane] : 0;
#pragma unroll
        for (int off = 1; off < 8; off <<= 1) {
            int u = __shfl_up_sync(0xffffffffu, v, off);
            if (lane >= off) v += u;
        }
        if (lane < 8) wsum[lane] = v;
    }
    __syncthreads();
    int exc = inc - s + (w > 0 ? wsum[w - 1] : 0);
#pragma unroll
    for (int i = 0; i < 8; i++) {
        int idx = base + i;
        if (idx < n) { g_rowptr[idx] = exc; g_fill[idx] = 0; }
        exc += d[i];
    }
    if (t == 255) g_bsum[blockIdx.x] = wsum[7];
}

__global__ void scan2_k(int nb, int n) {
    int lane = threadIdx.x;
    int a = (lane      < nb) ? g_bsum[lane]      : 0;
    int b = (lane + 32 < nb) ? g_bsum[lane + 32] : 0;
    int ia = a, ib = b;
#pragma unroll
    for (int off = 1; off < 32; off <<= 1) {
        int v = __shfl_up_sync(0xffffffffu, ia, off);
        if (lane >= off) ia += v;
        int u = __shfl_up_sync(0xffffffffu, ib, off);
        if (lane >= off) ib += u;
    }
    int sumA = __shfl_sync(0xffffffffu, ia, 31);
    g_boff[lane]      = ia - a;
    g_boff[lane + 32] = sumA + ib - b;
    if (lane == 31) g_rowptr[n] = sumA + ib;
    if (lane == 0) { g_mmint[0] = 0x7fffffff; g_mmint[1] = 0; }   // min/max init
    if (lane < 32) { if (lane + 1 <= 33) { g_acc[lane] = 0.f; if (lane == 0) g_acc[32] = 0.f; } }
}

__global__ void __launch_bounds__(256) scan3_k(int n) {
    int add = g_boff[blockIdx.x];
    int base = blockIdx.x * 2048 + threadIdx.x * 8;
#pragma unroll
    for (int i = 0; i < 8; i++) {
        int idx = base + i;
        if (idx < n) g_rowptr[idx] += add;
    }
}

__global__ void fill_k(const int* __restrict__ srcI,
                       const int* __restrict__ dstI, int e) {
    int i = blockIdx.x * blockDim.x + threadIdx.x;
    if (i >= e) return;
    int s = __ldg(srcI + i);
    int d = __ldg(dstI + i);
    int pos = atomicAdd(&g_fill[d], 1);
    g_csrc[g_rowptr[d] + pos] = s;
}

// ---------------- fused GEMM: [128-node tile] x [64x64 W] ----------------
// Epilogue: writes h*dinv as fp16 to g_tmp16 (128 B/node).
// MODE 0: X = Xin. MODE 1: X = g_h1 with bias+BN+ReLU applied on load.
template<int MODE>
__global__ void __launch_bounds__(256) gemm_fused_k(
    const float* __restrict__ Xin,
    const float* __restrict__ W,
    const float* __restrict__ b1,
    const float* __restrict__ gamma,
    const float* __restrict__ beta,
    int n)
{
    __shared__ float4 Xs4[64 * 32];
    __shared__ float4 Ws4[64 * 16];
    const float* X = (MODE == 0) ? Xin : g_h1;
    int t  = threadIdx.x;
    int n0 = blockIdx.x * 128;

    const float4* W4 = (const float4*)W;
    for (int i = t; i < 1024; i += 256) Ws4[i] = W4[i];

    const float rs = rsqrtf(1.0f + 1e-5f);
    float* Xsf = (float*)Xs4;
    for (int i = t; i < 2048; i += 256) {
        int node = i >> 4, c4 = i & 15;
        int gn = n0 + node;
        float4 v = make_float4(0.f, 0.f, 0.f, 0.f);
        if (gn < n) {
            v = ((const float4*)(X + (size_t)gn * 64))[c4];
            if (MODE == 1) {
                float4 gm = ((const float4*)gamma)[c4];
                float4 bt = ((const float4*)beta )[c4];
                float4 bb = ((const float4*)b1   )[c4];
                float a0 = rs * gm.x, a1 = rs * gm.y, a2 = rs * gm.z, a3 = rs * gm.w;
                v.x = fmaxf(fmaf(v.x + bb.x, a0, bt.x), 0.f);
                v.y = fmaxf(fmaf(v.y + bb.y, a1, bt.y), 0.f);
                v.z = fmaxf(fmaf(v.z + bb.z, a2, bt.z), 0.f);
                v.w = fmaxf(fmaf(v.w + bb.w, a3, bt.w), 0.f);
            }
        }
        int g = node >> 2, lo = node & 3;
        int sg = g ^ (c4 & 7);
        float* base = Xsf + (c4 * 4) * 128 + sg * 4 + lo;
        base[0]   = v.x;
        base[128] = v.y;
        base[256] = v.z;
        base[384] = v.w;
    }
    __syncthreads();

    int ng = t & 31;
    int og = t >> 5;
    ull acc2[4][4];
#pragma unroll
    for (int i = 0; i < 4; i++)
#pragma unroll
        for (int jp = 0; jp < 4; jp++) acc2[i][jp] = 0ull;

#pragma unroll 8
    for (int k = 0; k < 64; k++) {
        float4 xv = Xs4[k * 32 + (ng ^ ((k >> 2) & 7))];
        ulonglong2 wA = *(const ulonglong2*)&Ws4[k * 16 + og * 2];
        ulonglong2 wB = *(const ulonglong2*)&Ws4[k * 16 + og * 2 + 1];
        ull w2[4] = {wA.x, wA.y, wB.x, wB.y};
        float xa[4] = {xv.x, xv.y, xv.z, xv.w};
#pragma unroll
        for (int i = 0; i < 4; i++) {
            ull xd = pack2(xa[i], xa[i]);
#pragma unroll
            for (int jp = 0; jp < 4; jp++) ffma2(acc2[i][jp], xd, w2[jp]);
        }
    }

    int nb = n0 + 4 * ng;
    if (nb < n) {
        float4 dv = *(const float4*)(g_dinv + nb);
        float di[4] = {dv.x, dv.y, dv.z, dv.w};
#pragma unroll
        for (int i = 0; i < 4; i++) {
            int gn = nb + i;
            if (gn < n) {
                float2 p0 = unp(acc2[i][0]), p1 = unp(acc2[i][1]);
                float2 p2 = unp(acc2[i][2]), p3 = unp(acc2[i][3]);
                float s = di[i];
                __half2 h0 = __floats2half2_rn(p0.x * s, p0.y * s);
                __half2 h1 = __floats2half2_rn(p1.x * s, p1.y * s);
                __half2 h2 = __floats2half2_rn(p2.x * s, p2.y * s);
                __half2 h3 = __floats2half2_rn(p3.x * s, p3.y * s);
                uint4 pk;
                pk.x = *(unsigned*)&h0; pk.y = *(unsigned*)&h1;
                pk.z = *(unsigned*)&h2; pk.w = *(unsigned*)&h3;
                *(uint4*)(g_tmp16 + (size_t)gn * 64 + og * 8) = pk;
            }
        }
    }
}

// ---------------- CSR gather: out[d] = dinv[d] * sum_{s in N(d) u {d}} tmp16[s] ----
// 8 threads per node, each owns 8 half-columns (16 B).
__global__ void __launch_bounds__(256) gather_k(int which, int n) {
    int g = (blockIdx.x * blockDim.x + threadIdx.x) >> 3;
    int c = threadIdx.x & 7;
    if (g >= n) return;
    const uint4* T = (const uint4*)g_tmp16;   // 8 uint4 per node row
    float2 acc[4];
    {
        uint4 v = T[(size_t)g * 8 + c];       // self term (tmp2[d])
        acc[0] = __half22float2(*(__half2*)&v.x);
        acc[1] = __half22float2(*(__half2*)&v.y);
        acc[2] = __half22float2(*(__half2*)&v.z);
        acc[3] = __half22float2(*(__half2*)&v.w);
    }
    int j = g_rowptr[g], end = g_rowptr[g + 1];
    for (; j + 1 < end; j += 2) {
        int s0 = __ldg(g_csrc + j);
        int s1 = __ldg(g_csrc + j + 1);
        uint4 v0 = T[(size_t)s0 * 8 + c];
        uint4 v1 = T[(size_t)s1 * 8 + c];
        float2 a0 = __half22float2(*(__half2*)&v0.x), b0 = __half22float2(*(__half2*)&v1.x);
        float2 a1 = __half22float2(*(__half2*)&v0.y), b1 = __half22float2(*(__half2*)&v1.y);
        float2 a2 = __half22float2(*(__half2*)&v0.z), b2 = __half22float2(*(__half2*)&v1.z);
        float2 a3 = __half22float2(*(__half2*)&v0.w), b3 = __half22float2(*(__half2*)&v1.w);
        acc[0].x += a0.x + b0.x; acc[0].y += a0.y + b0.y;
        acc[1].x += a1.x + b1.x; acc[1].y += a1.y + b1.y;
        acc[2].x += a2.x + b2.x; acc[2].y += a2.y + b2.y;
        acc[3].x += a3.x + b3.x; acc[3].y += a3.y + b3.y;
    }
    if (j < end) {
        int s0 = __ldg(g_csrc + j);
        uint4 v0 = T[(size_t)s0 * 8 + c];
        float2 a0 = __half22float2(*(__half2*)&v0.x);
        float2 a1 = __half22float2(*(__half2*)&v0.y);
        float2 a2 = __half22float2(*(__half2*)&v0.z);
        float2 a3 = __half22float2(*(__half2*)&v0.w);
        acc[0].x += a0.x; acc[0].y += a0.y;
        acc[1].x += a1.x; acc[1].y += a1.y;
        acc[2].x += a2.x; acc[2].y += a2.y;
        acc[3].x += a3.x; acc[3].y += a3.y;
    }
    float dd = g_dinv[g];
    float* outp = (which ? g_h2 : g_h1) + (size_t)g * 64 + c * 8;
    ((float4*)outp)[0] = make_float4(acc[0].x * dd, acc[0].y * dd, acc[1].x * dd, acc[1].y * dd);
    ((float4*)outp)[1] = make_float4(acc[2].x * dd, acc[2].y * dd, acc[3].x * dd, acc[3].y * dd);
}

// ---------------- logits + softmax + entropy + wts + block min/max ----------------
__global__ void __launch_bounds__(128) logits_k(
    const float* __restrict__ b2,
    const float* __restrict__ W,    // [64,32] row-major
    const float* __restrict__ bb,   // [32]
    int n)
{
    __shared__ float4 Xs4[64 * 32];
    __shared__ float4 Wl4[64 * 8];
    __shared__ int smm[8];          // per-warp min/max (int-encoded)
    int t  = threadIdx.x;
    int n0 = blockIdx.x * 128;

    for (int i = t; i < 512; i += 128) Wl4[i] = ((const float4*)W)[i];

    float* Xsf = (float*)Xs4;
    for (int i = t; i < 2048; i += 128) {
        int node = i >> 4, c4 = i & 15;
        int gn = n0 + node;
        float4 v = make_float4(0.f, 0.f, 0.f, 0.f);
        if (gn < n) {
            v = ((const float4*)(g_h2 + (size_t)gn * 64))[c4];
            float4 b = ((const float4*)b2)[c4];
            v.x += b.x; v.y += b.y; v.z += b.z; v.w += b.w;
        }
        int g = node >> 2, lo = node & 3;
        int sg = g ^ (c4 & 7);
        float* base = Xsf + (c4 * 4) * 128 + sg * 4 + lo;
        base[0]   = v.x;
        base[128] = v.y;
        base[256] = v.z;
        base[384] = v.w;
    }
    __syncthreads();

    int ng = t & 31;
    int og = t >> 5;
    ull acc2[4][4];
    float4 bb0 = ((const float4*)bb)[og * 2];
    float4 bb1 = ((const float4*)bb)[og * 2 + 1];
    float bj[8] = {bb0.x, bb0.y, bb0.z, bb0.w, bb1.x, bb1.y, bb1.z, bb1.w};
#pragma unroll
    for (int i = 0; i < 4; i++)
#pragma unroll
        for (int jp = 0; jp < 4; jp++) acc2[i][jp] = pack2(bj[2 * jp], bj[2 * jp + 1]);

#pragma unroll 8
    for (int k = 0; k < 64; k++) {
        float4 xv = Xs4[k * 32 + (ng ^ ((k >> 2) & 7))];
        ulonglong2 wA = *(const ulonglong2*)&Wl4[k * 8 + og * 2];
        ulonglong2 wB = *(const ulonglong2*)&Wl4[k * 8 + og * 2 + 1];
        ull w2[4] = {wA.x, wA.y, wB.x, wB.y};
        float xa[4] = {xv.x, xv.y, xv.z, xv.w};
#pragma unroll
        for (int i = 0; i < 4; i++) {
            ull xd = pack2(xa[i], xa[i]);
#pragma unroll
            for (int jp = 0; jp < 4; jp++) ffma2(acc2[i][jp], xd, w2[jp]);
        }
    }
    __syncthreads();

    float* Ls = Xsf;
#pragma unroll
    for (int i = 0; i < 4; i++) {
        float2 p0 = unp(acc2[i][0]), p1 = unp(acc2[i][1]);
        float2 p2 = unp(acc2[i][2]), p3 = unp(acc2[i][3]);
        float* row = Ls + (4 * ng + i) * 33 + og * 8;
        row[0] = p0.x; row[1] = p0.y; row[2] = p1.x; row[3] = p1.y;
        row[4] = p2.x; row[5] = p2.y; row[6] = p3.x; row[7] = p3.y;
    }
    __syncthreads();

    int lane = t & 31;
    float wmn = 3.4e38f, wmx = 0.0f;
    for (int r = og; r < 128; r += 4) {
        int gn = n0 + r;
        float l = Ls[r * 33 + lane];
        float m = l;
#pragma unroll
        for (int off = 16; off; off >>= 1)
            m = fmaxf(m, __shfl_xor_sync(0xffffffffu, m, off));
        float p = expf(l - m);
        float sum = p;
#pragma unroll
        for (int off = 16; off; off >>= 1)
            sum += __shfl_xor_sync(0xffffffffu, sum, off);
        p /= sum;
        float term = -p * logf(p + 1e-9f);
#pragma unroll
        for (int off = 16; off; off >>= 1)
            term += __shfl_xor_sync(0xffffffffu, term, off);
        if (gn < n) {
            float wv = 1.0f / (term + 1e-10f);
            g_logits[(size_t)gn * 32 + lane] = l;
            if (lane == 0) {
                g_wts[gn] = wv;
                wmn = fminf(wmn, wv);
                wmx = fmaxf(wmx, wv);
            }
        }
    }
    if (lane == 0) {
        smm[og * 2]     = __float_as_int(wmn);
        smm[og * 2 + 1] = __float_as_int(wmx);
    }
    __syncthreads();
    if (t == 0) {
        int mn = smm[0], mx = smm[1];
#pragma unroll
        for (int i = 1; i < 4; i++) {
            mn = min(mn, smm[i * 2]);
            mx = max(mx, smm[i * 2 + 1]);
        }
        atomicMin(&g_mmint[0], mn);   // positive floats: int order == float order
        atomicMax(&g_mmint[1], mx);
    }
}

// ---------------- weighted sum ----------------
__global__ void wsum_k(int n) {
    __shared__ float sacc[8][33];
    int t = threadIdx.x, w = t >> 5, lane = t & 31;
    float mn = __int_as_float(g_mmint[0]);
    float den = __int_as_float(g_mmint[1]) - mn;
    float inv = den > 0.0f ? 1.0f / den : 0.0f;
    float acc = 0.0f, se = 0.0f;
    int warpG = blockIdx.x * 8 + w;
    int nwarp = gridDim.x * 8;
    for (int i = warpG; i < n; i += nwarp) {
        float e = expf((g_wts[i] - mn) * inv);
        acc += e * g_logits[(size_t)i * 32 + lane];
        se  += e;
    }
    sacc[w][lane] = acc;
    if (lane == 0) sacc[w][32] = se;
    __syncthreads();
    if (w == 0) {
        float a = sacc[0][lane];
#pragma unroll
        for (int r = 1; r < 8; r++) a += sacc[r][lane];
        atomicAdd(&g_acc[lane], a);
        if (lane == 0) {
            float b = sacc[0][32];
#pragma unroll
            for (int r = 1; r < 8; r++) b += sacc[r][32];
            atomicAdd(&g_acc[32], b);
        }
    }
}

// ---------------- final ----------------
__global__ void final_k(const float* __restrict__ w3,
                        const float* __restrict__ b3,
                        float* __restrict__ out) {
    int j = threadIdx.x;
    float invS = 1.0f / g_acc[32];
    float a = b3[j];
#pragma unroll
    for (int o = 0; o < 32; o++) a += (g_acc[o] * invS) * w3[o * 64 + j];
    out[j] = a;
}

// ---------------- launch ----------------
extern "C" void kernel_launch(void* const* d_in, const int* in_sizes, int n_in,
                              void* d_out, int out_size) {
    const float* x     = (const float*)d_in[0];
    const int*   ei    = (const int*)  d_in[1];
    const float* W1    = (const float*)d_in[2];
    const float* b1    = (const float*)d_in[3];
    const float* gamma = (const float*)d_in[4];
    const float* beta  = (const float*)d_in[5];
    const float* W2    = (const float*)d_in[6];
    const float* b2    = (const float*)d_in[7];
    const float* l2w   = (const float*)d_in[8];
    const float* l2b   = (const float*)d_in[9];
    const float* l3w   = (const float*)d_in[10];
    const float* l3b   = (const float*)d_in[11];
    float* out = (float*)d_out;

    int n = in_sizes[0] / 64;
    int e = in_sizes[1] / 2;
    const int* srcI = ei;
    const int* dstI = ei + e;

    int nb  = (n + 255) / 256;
    int eb  = (e + 255) / 256;
    int gb  = (n + 127) / 128;
    int gtb = (n * 8 + 255) / 256;
    int scb = (n + 2047) / 2048;

    deg_init_k <<<nb, 256>>>(n);
    deg_count_k<<<eb, 256>>>(dstI, e);
    scan1_k    <<<scb, 256>>>(n);
    scan2_k    <<<1, 32>>>(scb, n);
    scan3_k    <<<scb, 256>>>(n);
    fill_k     <<<eb, 256>>>(srcI, dstI, e);

    // layer 1
    gemm_fused_k<0><<<gb, 256>>>(x, W1, nullptr, nullptr, nullptr, n);
    gather_k       <<<gtb, 256>>>(0, n);

    // layer 2 (bias+BN+ReLU fused into loader)
    gemm_fused_k<1><<<gb, 256>>>(nullptr, W2, b1, gamma, beta, n);
    gather_k       <<<gtb, 256>>>(1, n);

    // readout
    logits_k  <<<gb, 128>>>(b2, l2w, l2b, n);
    wsum_k    <<<128, 256>>>(n);
    final_k   <<<1, 64>>>(l3w, l3b, out);
}

// round 7
// speedup vs baseline: 1.3308x; 1.3308x over previous
#include <cuda_runtime.h>

#define NMAX 100000
#define EMAX 1600000

typedef unsigned long long ull;

// ---------------- device scratch ----------------
__device__ float g_deg   [NMAX];
__device__ float g_dinv  [NMAX];
__device__ float g_tmp   [NMAX * 64];
__device__ float g_h1    [NMAX * 64];
__device__ float g_h2    [NMAX * 64];
__device__ float g_logits[NMAX * 32];
__device__ float g_wts   [NMAX];
__device__ int   g_rowptr[NMAX + 1];
__device__ int   g_fill  [NMAX];
__device__ int   g_csrc  [EMAX];
__device__ int   g_bsum  [64];
__device__ int   g_boff  [64];
__device__ int   g_mmint [2];    // int-encoded min/max of wts (all positive)
__device__ float g_acc   [33];

// ---------------- f32x2 packed helpers ----------------
__device__ __forceinline__ ull pack2(float a, float b) {
    ull r; unsigned ia = __float_as_uint(a), ib = __float_as_uint(b);
    asm("mov.b64 %0, {%1, %2};" : "=l"(r) : "r"(ia), "r"(ib));
    return r;
}
__device__ __forceinline__ void ffma2(ull& d, ull a, ull b) {
    asm("fma.rn.f32x2 %0, %1, %2, %0;" : "+l"(d) : "l"(a), "l"(b));
}
__device__ __forceinline__ float2 unp(ull v) {
    float2 r; unsigned lo = (unsigned)v, hi = (unsigned)(v >> 32);
    r.x = __uint_as_float(lo); r.y = __uint_as_float(hi);
    return r;
}

// ---------------- degree ----------------
__global__ void deg_init_k(int n) {
    int i = blockIdx.x * blockDim.x + threadIdx.x;
    if (i < n) g_deg[i] = 1.0f;   // self-loop
}
__global__ void deg_count_k(const int* __restrict__ dstI, int e) {
    int i = blockIdx.x * blockDim.x + threadIdx.x;
    if (i < e) atomicAdd(&g_deg[dstI[i]], 1.0f);
}

// ---------------- parallel CSR rowptr scan (3 stages) ----------------
__global__ void __launch_bounds__(256) scan1_k(int n) {
    __shared__ int wsum[8];
    int t = threadIdx.x;
    int base = blockIdx.x * 2048 + t * 8;
    int d[8]; int s = 0;
#pragma unroll
    for (int i = 0; i < 8; i++) {
        int idx = base + i;
        float dg = (idx < n) ? g_deg[idx] : 1.0f;
        if (idx < n) g_dinv[idx] = rsqrtf(dg);
        d[i] = (idx < n) ? (int)dg - 1 : 0;
        s += d[i];
    }
    int lane = t & 31, w = t >> 5;
    int inc = s;
#pragma unroll
    for (int off = 1; off < 32; off <<= 1) {
        int v = __shfl_up_sync(0xffffffffu, inc, off);
        if (lane >= off) inc += v;
    }
    if (lane == 31) wsum[w] = inc;
    __syncthreads();
    if (w == 0) {
        int v = (lane < 8) ? wsum[lane] : 0;
#pragma unroll
        for (int off = 1; off < 8; off <<= 1) {
            int u = __shfl_up_sync(0xffffffffu, v, off);
            if (lane >= off) v += u;
        }
        if (lane < 8) wsum[lane] = v;
    }
    __syncthreads();
    int exc = inc - s + (w > 0 ? wsum[w - 1] : 0);
#pragma unroll
    for (int i = 0; i < 8; i++) {
        int idx = base + i;
        if (idx < n) { g_rowptr[idx] = exc; g_fill[idx] = 0; }
        exc += d[i];
    }
    if (t == 255) g_bsum[blockIdx.x] = wsum[7];
}

__global__ void scan2_k(int nb, int n) {
    int lane = threadIdx.x;
    int a = (lane      < nb) ? g_bsum[lane]      : 0;
    int b = (lane + 32 < nb) ? g_bsum[lane + 32] : 0;
    int ia = a, ib = b;
#pragma unroll
    for (int off = 1; off < 32; off <<= 1) {
        int v = __shfl_up_sync(0xffffffffu, ia, off);
        if (lane >= off) ia += v;
        int u = __shfl_up_sync(0xffffffffu, ib, off);
        if (lane >= off) ib += u;
    }
    int sumA = __shfl_sync(0xffffffffu, ia, 31);
    g_boff[lane]      = ia - a;
    g_boff[lane + 32] = sumA + ib - b;
    if (lane == 31) g_rowptr[n] = sumA + ib;
    if (lane == 0) { g_mmint[0] = 0x7fffffff; g_mmint[1] = 0; }
    g_acc[lane] = 0.f;
    if (lane == 0) g_acc[32] = 0.f;
}

__global__ void __launch_bounds__(256) scan3_k(int n) {
    int add = g_boff[blockIdx.x];
    int base = blockIdx.x * 2048 + threadIdx.x * 8;
#pragma unroll
    for (int i = 0; i < 8; i++) {
        int idx = base + i;
        if (idx < n) g_rowptr[idx] += add;
    }
}

__global__ void fill_k(const int* __restrict__ srcI,
                       const int* __restrict__ dstI, int e) {
    int i = blockIdx.x * blockDim.x + threadIdx.x;
    if (i >= e) return;
    int s = __ldg(srcI + i);
    int d = __ldg(dstI + i);
    int pos = atomicAdd(&g_fill[d], 1);
    g_csrc[g_rowptr[d] + pos] = s;
}

// ---------------- fused GEMM: [128-node tile] x [64x64 W] ----------------
template<int MODE>
__global__ void __launch_bounds__(256) gemm_fused_k(
    const float* __restrict__ Xin,
    const float* __restrict__ W,
    const float* __restrict__ b1,
    const float* __restrict__ gamma,
    const float* __restrict__ beta,
    int n)
{
    __shared__ float4 Xs4[64 * 32];
    __shared__ float4 Ws4[64 * 16];
    const float* X = (MODE == 0) ? Xin : g_h1;
    int t  = threadIdx.x;
    int n0 = blockIdx.x * 128;

    const float4* W4 = (const float4*)W;
    for (int i = t; i < 1024; i += 256) Ws4[i] = W4[i];

    const float rs = rsqrtf(1.0f + 1e-5f);
    float* Xsf = (float*)Xs4;
    for (int i = t; i < 2048; i += 256) {
        int node = i >> 4, c4 = i & 15;
        int gn = n0 + node;
        float4 v = make_float4(0.f, 0.f, 0.f, 0.f);
        if (gn < n) {
            v = ((const float4*)(X + (size_t)gn * 64))[c4];
            if (MODE == 1) {
                float4 gm = ((const float4*)gamma)[c4];
                float4 bt = ((const float4*)beta )[c4];
                float4 bb = ((const float4*)b1   )[c4];
                float a0 = rs * gm.x, a1 = rs * gm.y, a2 = rs * gm.z, a3 = rs * gm.w;
                v.x = fmaxf(fmaf(v.x + bb.x, a0, bt.x), 0.f);
                v.y = fmaxf(fmaf(v.y + bb.y, a1, bt.y), 0.f);
                v.z = fmaxf(fmaf(v.z + bb.z, a2, bt.z), 0.f);
                v.w = fmaxf(fmaf(v.w + bb.w, a3, bt.w), 0.f);
            }
        }
        int g = node >> 2, lo = node & 3;
        int sg = g ^ (c4 & 7);
        float* base = Xsf + (c4 * 4) * 128 + sg * 4 + lo;
        base[0]   = v.x;
        base[128] = v.y;
        base[256] = v.z;
        base[384] = v.w;
    }
    __syncthreads();

    int ng = t & 31;
    int og = t >> 5;
    ull acc2[4][4];
#pragma unroll
    for (int i = 0; i < 4; i++)
#pragma unroll
        for (int jp = 0; jp < 4; jp++) acc2[i][jp] = 0ull;

#pragma unroll 8
    for (int k = 0; k < 64; k++) {
        float4 xv = Xs4[k * 32 + (ng ^ ((k >> 2) & 7))];
        ulonglong2 wA = *(const ulonglong2*)&Ws4[k * 16 + og * 2];
        ulonglong2 wB = *(const ulonglong2*)&Ws4[k * 16 + og * 2 + 1];
        ull w2[4] = {wA.x, wA.y, wB.x, wB.y};
        float xa[4] = {xv.x, xv.y, xv.z, xv.w};
#pragma unroll
        for (int i = 0; i < 4; i++) {
            ull xd = pack2(xa[i], xa[i]);
#pragma unroll
            for (int jp = 0; jp < 4; jp++) ffma2(acc2[i][jp], xd, w2[jp]);
        }
    }

    int nb = n0 + 4 * ng;
#pragma unroll
    for (int i = 0; i < 4; i++) {
        int gn = nb + i;
        if (gn < n) {
            float2 p0 = unp(acc2[i][0]), p1 = unp(acc2[i][1]);
            float2 p2 = unp(acc2[i][2]), p3 = unp(acc2[i][3]);
            float4* tp = (float4*)(g_tmp + (size_t)gn * 64 + og * 8);
            tp[0] = make_float4(p0.x, p0.y, p1.x, p1.y);
            tp[1] = make_float4(p2.x, p2.y, p3.x, p3.y);
        }
    }
}

// ---------------- CSR gather (fp32, 16 thr/node, 4-edge unroll) ----------------
__global__ void __launch_bounds__(256) gather_k(int which, int n) {
    int g = (blockIdx.x * blockDim.x + threadIdx.x) >> 4;
    int c = threadIdx.x & 15;
    if (g >= n) return;
    float dd = g_dinv[g];
    float4 acc = ((const float4*)(g_tmp + (size_t)g * 64))[c];
    float s2 = dd * dd;
    acc.x *= s2; acc.y *= s2; acc.z *= s2; acc.w *= s2;
    int j = g_rowptr[g], end = g_rowptr[g + 1];
    for (; j + 4 <= end; j += 4) {
        int s0 = __ldg(g_csrc + j);
        int s1 = __ldg(g_csrc + j + 1);
        int s2i = __ldg(g_csrc + j + 2);
        int s3 = __ldg(g_csrc + j + 3);
        float n0 = g_dinv[s0] * dd;
        float n1 = g_dinv[s1] * dd;
        float n2 = g_dinv[s2i] * dd;
        float n3 = g_dinv[s3] * dd;
        float4 v0 = ((const float4*)(g_tmp + (size_t)s0  * 64))[c];
        float4 v1 = ((const float4*)(g_tmp + (size_t)s1  * 64))[c];
        float4 v2 = ((const float4*)(g_tmp + (size_t)s2i * 64))[c];
        float4 v3 = ((const float4*)(g_tmp + (size_t)s3  * 64))[c];
        acc.x = fmaf(v0.x, n0, acc.x); acc.y = fmaf(v0.y, n0, acc.y);
        acc.z = fmaf(v0.z, n0, acc.z); acc.w = fmaf(v0.w, n0, acc.w);
        acc.x = fmaf(v1.x, n1, acc.x); acc.y = fmaf(v1.y, n1, acc.y);
        acc.z = fmaf(v1.z, n1, acc.z); acc.w = fmaf(v1.w, n1, acc.w);
        acc.x = fmaf(v2.x, n2, acc.x); acc.y = fmaf(v2.y, n2, acc.y);
        acc.z = fmaf(v2.z, n2, acc.z); acc.w = fmaf(v2.w, n2, acc.w);
        acc.x = fmaf(v3.x, n3, acc.x); acc.y = fmaf(v3.y, n3, acc.y);
        acc.z = fmaf(v3.z, n3, acc.z); acc.w = fmaf(v3.w, n3, acc.w);
    }
    for (; j < end; j++) {
        int s0 = __ldg(g_csrc + j);
        float n0 = g_dinv[s0] * dd;
        float4 v0 = ((const float4*)(g_tmp + (size_t)s0 * 64))[c];
        acc.x = fmaf(v0.x, n0, acc.x);
        acc.y = fmaf(v0.y, n0, acc.y);
        acc.z = fmaf(v0.z, n0, acc.z);
        acc.w = fmaf(v0.w, n0, acc.w);
    }
    float* outp = which ? g_h2 : g_h1;
    ((float4*)(outp + (size_t)g * 64))[c] = acc;
}

// ---------------- logits + softmax + entropy + wts + fused min/max ----------------
__global__ void __launch_bounds__(128) logits_k(
    const float* __restrict__ b2,
    const float* __restrict__ W,    // [64,32] row-major
    const float* __restrict__ bb,   // [32]
    int n)
{
    __shared__ float4 Xs4[64 * 32];
    __shared__ float4 Wl4[64 * 8];
    __shared__ int smm[8];
    int t  = threadIdx.x;
    int n0 = blockIdx.x * 128;

    for (int i = t; i < 512; i += 128) Wl4[i] = ((const float4*)W)[i];

    float* Xsf = (float*)Xs4;
    for (int i = t; i < 2048; i += 128) {
        int node = i >> 4, c4 = i & 15;
        int gn = n0 + node;
        float4 v = make_float4(0.f, 0.f, 0.f, 0.f);
        if (gn < n) {
            v = ((const float4*)(g_h2 + (size_t)gn * 64))[c4];
            float4 b = ((const float4*)b2)[c4];
            v.x += b.x; v.y += b.y; v.z += b.z; v.w += b.w;
        }
        int g = node >> 2, lo = node & 3;
        int sg = g ^ (c4 & 7);
        float* base = Xsf + (c4 * 4) * 128 + sg * 4 + lo;
        base[0]   = v.x;
        base[128] = v.y;
        base[256] = v.z;
        base[384] = v.w;
    }
    __syncthreads();

    int ng = t & 31;
    int og = t >> 5;
    ull acc2[4][4];
    float4 bb0 = ((const float4*)bb)[og * 2];
    float4 bb1 = ((const float4*)bb)[og * 2 + 1];
    float bj[8] = {bb0.x, bb0.y, bb0.z, bb0.w, bb1.x, bb1.y, bb1.z, bb1.w};
#pragma unroll
    for (int i = 0; i < 4; i++)
#pragma unroll
        for (int jp = 0; jp < 4; jp++) acc2[i][jp] = pack2(bj[2 * jp], bj[2 * jp + 1]);

#pragma unroll 8
    for (int k = 0; k < 64; k++) {
        float4 xv = Xs4[k * 32 + (ng ^ ((k >> 2) & 7))];
        ulonglong2 wA = *(const ulonglong2*)&Wl4[k * 8 + og * 2];
        ulonglong2 wB = *(const ulonglong2*)&Wl4[k * 8 + og * 2 + 1];
        ull w2[4] = {wA.x, wA.y, wB.x, wB.y};
        float xa[4] = {xv.x, xv.y, xv.z, xv.w};
#pragma unroll
        for (int i = 0; i < 4; i++) {
            ull xd = pack2(xa[i], xa[i]);
#pragma unroll
            for (int jp = 0; jp < 4; jp++) ffma2(acc2[i][jp], xd, w2[jp]);
        }
    }
    __syncthreads();

    float* Ls = Xsf;
#pragma unroll
    for (int i = 0; i < 4; i++) {
        float2 p0 = unp(acc2[i][0]), p1 = unp(acc2[i][1]);
        float2 p2 = unp(acc2[i][2]), p3 = unp(acc2[i][3]);
        float* row = Ls + (4 * ng + i) * 33 + og * 8;
        row[0] = p0.x; row[1] = p0.y; row[2] = p1.x; row[3] = p1.y;
        row[4] = p2.x; row[5] = p2.y; row[6] = p3.x; row[7] = p3.y;
    }
    __syncthreads();

    int lane = t & 31;
    float wmn = 3.4e38f, wmx = 0.0f;
    for (int r = og; r < 128; r += 4) {
        int gn = n0 + r;
        float l = Ls[r * 33 + lane];
        float m = l;
#pragma unroll
        for (int off = 16; off; off >>= 1)
            m = fmaxf(m, __shfl_xor_sync(0xffffffffu, m, off));
        float p = expf(l - m);
        float sum = p;
#pragma unroll
        for (int off = 16; off; off >>= 1)
            sum += __shfl_xor_sync(0xffffffffu, sum, off);
        p /= sum;
        float term = -p * logf(p + 1e-9f);
#pragma unroll
        for (int off = 16; off; off >>= 1)
            term += __shfl_xor_sync(0xffffffffu, term, off);
        if (gn < n) {
            float wv = 1.0f / (term + 1e-10f);
            g_logits[(size_t)gn * 32 + lane] = l;
            if (lane == 0) {
                g_wts[gn] = wv;
                wmn = fminf(wmn, wv);
                wmx = fmaxf(wmx, wv);
            }
        }
    }
    if (lane == 0) {
        smm[og * 2]     = __float_as_int(wmn);
        smm[og * 2 + 1] = __float_as_int(wmx);
    }
    __syncthreads();
    if (t == 0) {
        int mn = smm[0], mx = smm[1];
#pragma unroll
        for (int i = 1; i < 4; i++) {
            mn = min(mn, smm[i * 2]);
            mx = max(mx, smm[i * 2 + 1]);
        }
        atomicMin(&g_mmint[0], mn);   // positive floats: int order == float order
        atomicMax(&g_mmint[1], mx);
    }
}

// ---------------- weighted sum ----------------
__global__ void wsum_k(int n) {
    __shared__ float sacc[8][33];
    int t = threadIdx.x, w = t >> 5, lane = t & 31;
    float mn = __int_as_float(g_mmint[0]);
    float den = __int_as_float(g_mmint[1]) - mn;
    float inv = den > 0.0f ? 1.0f / den : 0.0f;
    float acc = 0.0f, se = 0.0f;
    int warpG = blockIdx.x * 8 + w;
    int nwarp = gridDim.x * 8;
    for (int i = warpG; i < n; i += nwarp) {
        float e = expf((g_wts[i] - mn) * inv);
        acc += e * g_logits[(size_t)i * 32 + lane];
        se  += e;
    }
    sacc[w][lane] = acc;
    if (lane == 0) sacc[w][32] = se;
    __syncthreads();
    if (w == 0) {
        float a = sacc[0][lane];
#pragma unroll
        for (int r = 1; r < 8; r++) a += sacc[r][lane];
        atomicAdd(&g_acc[lane], a);
        if (lane == 0) {
            float b = sacc[0][32];
#pragma unroll
            for (int r = 1; r < 8; r++) b += sacc[r][32];
            atomicAdd(&g_acc[32], b);
        }
    }
}

// ---------------- final ----------------
__global__ void final_k(const float* __restrict__ w3,
                        const float* __restrict__ b3,
                        float* __restrict__ out) {
    int j = threadIdx.x;
    float invS = 1.0f / g_acc[32];
    float a = b3[j];
#pragma unroll
    for (int o = 0; o < 32; o++) a += (g_acc[o] * invS) * w3[o * 64 + j];
    out[j] = a;
}

// ---------------- launch ----------------
extern "C" void kernel_launch(void* const* d_in, const int* in_sizes, int n_in,
                              void* d_out, int out_size) {
    const float* x     = (const float*)d_in[0];
    const int*   ei    = (const int*)  d_in[1];
    const float* W1    = (const float*)d_in[2];
    const float* b1    = (const float*)d_in[3];
    const float* gamma = (const float*)d_in[4];
    const float* beta  = (const float*)d_in[5];
    const float* W2    = (const float*)d_in[6];
    const float* b2    = (const float*)d_in[7];
    const float* l2w   = (const float*)d_in[8];
    const float* l2b   = (const float*)d_in[9];
    const float* l3w   = (const float*)d_in[10];
    const float* l3b   = (const float*)d_in[11];
    float* out = (float*)d_out;

    int n = in_sizes[0] / 64;
    int e = in_sizes[1] / 2;
    const int* srcI = ei;
    const int* dstI = ei + e;

    int nb  = (n + 255) / 256;
    int eb  = (e + 255) / 256;
    int gb  = (n + 127) / 128;
    int gtb = (n * 16 + 255) / 256;
    int scb = (n + 2047) / 2048;

    deg_init_k <<<nb, 256>>>(n);
    deg_count_k<<<eb, 256>>>(dstI, e);
    scan1_k    <<<scb, 256>>>(n);
    scan2_k    <<<1, 32>>>(scb, n);
    scan3_k    <<<scb, 256>>>(n);
    fill_k     <<<eb, 256>>>(srcI, dstI, e);

    // layer 1
    gemm_fused_k<0><<<gb, 256>>>(x, W1, nullptr, nullptr, nullptr, n);
    gather_k       <<<gtb, 256>>>(0, n);

    // layer 2 (bias+BN+ReLU fused into loader)
    gemm_fused_k<1><<<gb, 256>>>(nullptr, W2, b1, gamma, beta, n);
    gather_k       <<<gtb, 256>>>(1, n);

    // readout
    logits_k  <<<gb, 128>>>(b2, l2w, l2b, n);
    wsum_k    <<<128, 256>>>(n);
    final_k   <<<1, 64>>>(l3w, l3b, out);
}

// round 8
// speedup vs baseline: 1.4527x; 1.0916x over previous
#include <cuda_runtime.h>
#include <cuda_fp16.h>

#define NMAX 100000
#define EMAX 1600000

typedef unsigned long long ull;

// ---------------- device scratch ----------------
__device__ float  g_deg   [NMAX];
__device__ float  g_dinv  [NMAX];
__device__ __half g_tmp16 [NMAX * 64];   // h * dinv[src], fp16, 128 B/row
__device__ float  g_h1    [NMAX * 64];
__device__ float  g_h2    [NMAX * 64];
__device__ float  g_logits[NMAX * 32];
__device__ float  g_wts   [NMAX];
__device__ int    g_rowptr[NMAX + 1];
__device__ int    g_fill  [NMAX];
__device__ int    g_csrc  [EMAX];
__device__ int    g_bsum  [64];
__device__ int    g_boff  [64];
__device__ int    g_mmint [2];
__device__ float  g_acc   [33];

// ---------------- f32x2 packed helpers ----------------
__device__ __forceinline__ ull pack2(float a, float b) {
    ull r; unsigned ia = __float_as_uint(a), ib = __float_as_uint(b);
    asm("mov.b64 %0, {%1, %2};" : "=l"(r) : "r"(ia), "r"(ib));
    return r;
}
__device__ __forceinline__ void ffma2(ull& d, ull a, ull b) {
    asm("fma.rn.f32x2 %0, %1, %2, %0;" : "+l"(d) : "l"(a), "l"(b));
}
__device__ __forceinline__ void fadd2(ull& d, ull a) {
    asm("add.rn.f32x2 %0, %0, %1;" : "+l"(d) : "l"(a));
}
__device__ __forceinline__ float2 unp(ull v) {
    float2 r; unsigned lo = (unsigned)v, hi = (unsigned)(v >> 32);
    r.x = __uint_as_float(lo); r.y = __uint_as_float(hi);
    return r;
}
__device__ __forceinline__ ull cvt2(unsigned h2bits) {
    float2 f = __half22float2(*(__half2*)&h2bits);
    return pack2(f.x, f.y);
}

// ---------------- degree ----------------
__global__ void deg_init_k(int n) {
    int i = blockIdx.x * blockDim.x + threadIdx.x;
    if (i < n) g_deg[i] = 1.0f;   // self-loop
}
__global__ void deg_count_k(const int* __restrict__ dstI, int e) {
    int i = blockIdx.x * blockDim.x + threadIdx.x;
    if (i < e) atomicAdd(&g_deg[dstI[i]], 1.0f);
}

// ---------------- parallel CSR rowptr scan (3 stages) ----------------
__global__ void __launch_bounds__(256) scan1_k(int n) {
    __shared__ int wsum[8];
    int t = threadIdx.x;
    int base = blockIdx.x * 2048 + t * 8;
    int d[8]; int s = 0;
#pragma unroll
    for (int i = 0; i < 8; i++) {
        int idx = base + i;
        float dg = (idx < n) ? g_deg[idx] : 1.0f;
        if (idx < n) g_dinv[idx] = rsqrtf(dg);
        d[i] = (idx < n) ? (int)dg - 1 : 0;
        s += d[i];
    }
    int lane = t & 31, w = t >> 5;
    int inc = s;
#pragma unroll
    for (int off = 1; off < 32; off <<= 1) {
        int v = __shfl_up_sync(0xffffffffu, inc, off);
        if (lane >= off) inc += v;
    }
    if (lane == 31) wsum[w] = inc;
    __syncthreads();
    if (w == 0) {
        int v = (lane < 8) ? wsum[lane] : 0;
#pragma unroll
        for (int off = 1; off < 8; off <<= 1) {
            int u = __shfl_up_sync(0xffffffffu, v, off);
            if (lane >= off) v += u;
        }
        if (lane < 8) wsum[lane] = v;
    }
    __syncthreads();
    int exc = inc - s + (w > 0 ? wsum[w - 1] : 0);
#pragma unroll
    for (int i = 0; i < 8; i++) {
        int idx = base + i;
        if (idx < n) { g_rowptr[idx] = exc; g_fill[idx] = 0; }
        exc += d[i];
    }
    if (t == 255) g_bsum[blockIdx.x] = wsum[7];
}

__global__ void scan2_k(int nb, int n) {
    int lane = threadIdx.x;
    int a = (lane      < nb) ? g_bsum[lane]      : 0;
    int b = (lane + 32 < nb) ? g_bsum[lane + 32] : 0;
    int ia = a, ib = b;
#pragma unroll
    for (int off = 1; off < 32; off <<= 1) {
        int v = __shfl_up_sync(0xffffffffu, ia, off);
        if (lane >= off) ia += v;
        int u = __shfl_up_sync(0xffffffffu, ib, off);
        if (lane >= off) ib += u;
    }
    int sumA = __shfl_sync(0xffffffffu, ia, 31);
    g_boff[lane]      = ia - a;
    g_boff[lane + 32] = sumA + ib - b;
    if (lane == 31) g_rowptr[n] = sumA + ib;
    if (lane == 0) { g_mmint[0] = 0x7fffffff; g_mmint[1] = 0; }
    g_acc[lane] = 0.f;
    if (lane == 0) g_acc[32] = 0.f;
}

__global__ void __launch_bounds__(256) scan3_k(int n) {
    int add = g_boff[blockIdx.x];
    int base = blockIdx.x * 2048 + threadIdx.x * 8;
#pragma unroll
    for (int i = 0; i < 8; i++) {
        int idx = base + i;
        if (idx < n) g_rowptr[idx] += add;
    }
}

__global__ void fill_k(const int* __restrict__ srcI,
                       const int* __restrict__ dstI, int e) {
    int i = blockIdx.x * blockDim.x + threadIdx.x;
    if (i >= e) return;
    int s = __ldg(srcI + i);
    int d = __ldg(dstI + i);
    int pos = atomicAdd(&g_fill[d], 1);
    g_csrc[g_rowptr[d] + pos] = s;
}

// ---------------- fused GEMM: [128-node tile] x [64x64 W] ----------------
// Epilogue writes h*dinv as fp16 (128 B/node).
template<int MODE>
__global__ void __launch_bounds__(256) gemm_fused_k(
    const float* __restrict__ Xin,
    const float* __restrict__ W,
    const float* __restrict__ b1,
    const float* __restrict__ gamma,
    const float* __restrict__ beta,
    int n)
{
    __shared__ float4 Xs4[64 * 32];
    __shared__ float4 Ws4[64 * 16];
    const float* X = (MODE == 0) ? Xin : g_h1;
    int t  = threadIdx.x;
    int n0 = blockIdx.x * 128;

    const float4* W4 = (const float4*)W;
    for (int i = t; i < 1024; i += 256) Ws4[i] = W4[i];

    const float rs = rsqrtf(1.0f + 1e-5f);
    float* Xsf = (float*)Xs4;
    for (int i = t; i < 2048; i += 256) {
        int node = i >> 4, c4 = i & 15;
        int gn = n0 + node;
        float4 v = make_float4(0.f, 0.f, 0.f, 0.f);
        if (gn < n) {
            v = ((const float4*)(X + (size_t)gn * 64))[c4];
            if (MODE == 1) {
                float4 gm = ((const float4*)gamma)[c4];
                float4 bt = ((const float4*)beta )[c4];
                float4 bb = ((const float4*)b1   )[c4];
                float a0 = rs * gm.x, a1 = rs * gm.y, a2 = rs * gm.z, a3 = rs * gm.w;
                v.x = fmaxf(fmaf(v.x + bb.x, a0, bt.x), 0.f);
                v.y = fmaxf(fmaf(v.y + bb.y, a1, bt.y), 0.f);
                v.z = fmaxf(fmaf(v.z + bb.z, a2, bt.z), 0.f);
                v.w = fmaxf(fmaf(v.w + bb.w, a3, bt.w), 0.f);
            }
        }
        int g = node >> 2, lo = node & 3;
        int sg = g ^ (c4 & 7);
        float* base = Xsf + (c4 * 4) * 128 + sg * 4 + lo;
        base[0]   = v.x;
        base[128] = v.y;
        base[256] = v.z;
        base[384] = v.w;
    }
    __syncthreads();

    int ng = t & 31;
    int og = t >> 5;
    ull acc2[4][4];
#pragma unroll
    for (int i = 0; i < 4; i++)
#pragma unroll
        for (int jp = 0; jp < 4; jp++) acc2[i][jp] = 0ull;

#pragma unroll 8
    for (int k = 0; k < 64; k++) {
        float4 xv = Xs4[k * 32 + (ng ^ ((k >> 2) & 7))];
        ulonglong2 wA = *(const ulonglong2*)&Ws4[k * 16 + og * 2];
        ulonglong2 wB = *(const ulonglong2*)&Ws4[k * 16 + og * 2 + 1];
        ull w2[4] = {wA.x, wA.y, wB.x, wB.y};
        float xa[4] = {xv.x, xv.y, xv.z, xv.w};
#pragma unroll
        for (int i = 0; i < 4; i++) {
            ull xd = pack2(xa[i], xa[i]);
#pragma unroll
            for (int jp = 0; jp < 4; jp++) ffma2(acc2[i][jp], xd, w2[jp]);
        }
    }

    int nb = n0 + 4 * ng;
    if (nb < n) {
        float4 dv = *(const float4*)(g_dinv + nb);
        float di[4] = {dv.x, dv.y, dv.z, dv.w};
#pragma unroll
        for (int i = 0; i < 4; i++) {
            int gn = nb + i;
            if (gn < n) {
                float2 p0 = unp(acc2[i][0]), p1 = unp(acc2[i][1]);
                float2 p2 = unp(acc2[i][2]), p3 = unp(acc2[i][3]);
                float s = di[i];
                __half2 h0 = __floats2half2_rn(p0.x * s, p0.y * s);
                __half2 h1 = __floats2half2_rn(p1.x * s, p1.y * s);
                __half2 h2 = __floats2half2_rn(p2.x * s, p2.y * s);
                __half2 h3 = __floats2half2_rn(p3.x * s, p3.y * s);
                uint4 pk;
                pk.x = *(unsigned*)&h0; pk.y = *(unsigned*)&h1;
                pk.z = *(unsigned*)&h2; pk.w = *(unsigned*)&h3;
                *(uint4*)(g_tmp16 + (size_t)gn * 64 + og * 8) = pk;
            }
        }
    }
}

// ---------------- CSR gather: out[d] = dinv[d] * sum tmp16[s] ----------------
// SAME geometry as the fp32 winner: 16 threads/node; each lane owns 4 halves (8 B).
__global__ void __launch_bounds__(256) gather_k(int which, int n) {
    int g = (blockIdx.x * blockDim.x + threadIdx.x) >> 4;
    int c = threadIdx.x & 15;
    if (g >= n) return;
    const uint2* T = (const uint2*)g_tmp16;   // 16 uint2 per node row
    ull a01, a23;
    {
        uint2 v = T[(size_t)g * 16 + c];      // self term
        a01 = cvt2(v.x);
        a23 = cvt2(v.y);
    }
    int j = g_rowptr[g], end = g_rowptr[g + 1];
    for (; j + 4 <= end; j += 4) {
        int s0 = __ldg(g_csrc + j);
        int s1 = __ldg(g_csrc + j + 1);
        int s2 = __ldg(g_csrc + j + 2);
        int s3 = __ldg(g_csrc + j + 3);
        uint2 v0 = T[(size_t)s0 * 16 + c];
        uint2 v1 = T[(size_t)s1 * 16 + c];
        uint2 v2 = T[(size_t)s2 * 16 + c];
        uint2 v3 = T[(size_t)s3 * 16 + c];
        fadd2(a01, cvt2(v0.x)); fadd2(a23, cvt2(v0.y));
        fadd2(a01, cvt2(v1.x)); fadd2(a23, cvt2(v1.y));
        fadd2(a01, cvt2(v2.x)); fadd2(a23, cvt2(v2.y));
        fadd2(a01, cvt2(v3.x)); fadd2(a23, cvt2(v3.y));
    }
    for (; j < end; j++) {
        int s0 = __ldg(g_csrc + j);
        uint2 v0 = T[(size_t)s0 * 16 + c];
        fadd2(a01, cvt2(v0.x)); fadd2(a23, cvt2(v0.y));
    }
    float dd = g_dinv[g];
    float2 r0 = unp(a01), r1 = unp(a23);
    float* outp = which ? g_h2 : g_h1;
    ((float4*)(outp + (size_t)g * 64))[c] =
        make_float4(r0.x * dd, r0.y * dd, r1.x * dd, r1.y * dd);
}

// ---------------- logits + softmax + entropy + wts + fused min/max ----------------
__global__ void __launch_bounds__(128) logits_k(
    const float* __restrict__ b2,
    const float* __restrict__ W,    // [64,32] row-major
    const float* __restrict__ bb,   // [32]
    int n)
{
    __shared__ float4 Xs4[64 * 32];
    __shared__ float4 Wl4[64 * 8];
    __shared__ int smm[8];
    int t  = threadIdx.x;
    int n0 = blockIdx.x * 128;

    for (int i = t; i < 512; i += 128) Wl4[i] = ((const float4*)W)[i];

    float* Xsf = (float*)Xs4;
    for (int i = t; i < 2048; i += 128) {
        int node = i >> 4, c4 = i & 15;
        int gn = n0 + node;
        float4 v = make_float4(0.f, 0.f, 0.f, 0.f);
        if (gn < n) {
            v = ((const float4*)(g_h2 + (size_t)gn * 64))[c4];
            float4 b = ((const float4*)b2)[c4];
            v.x += b.x; v.y += b.y; v.z += b.z; v.w += b.w;
        }
        int g = node >> 2, lo = node & 3;
        int sg = g ^ (c4 & 7);
        float* base = Xsf + (c4 * 4) * 128 + sg * 4 + lo;
        base[0]   = v.x;
        base[128] = v.y;
        base[256] = v.z;
        base[384] = v.w;
    }
    __syncthreads();

    int ng = t & 31;
    int og = t >> 5;
    ull acc2[4][4];
    float4 bb0 = ((const float4*)bb)[og * 2];
    float4 bb1 = ((const float4*)bb)[og * 2 + 1];
    float bj[8] = {bb0.x, bb0.y, bb0.z, bb0.w, bb1.x, bb1.y, bb1.z, bb1.w};
#pragma unroll
    for (int i = 0; i < 4; i++)
#pragma unroll
        for (int jp = 0; jp < 4; jp++) acc2[i][jp] = pack2(bj[2 * jp], bj[2 * jp + 1]);

#pragma unroll 8
    for (int k = 0; k < 64; k++) {
        float4 xv = Xs4[k * 32 + (ng ^ ((k >> 2) & 7))];
        ulonglong2 wA = *(const ulonglong2*)&Wl4[k * 8 + og * 2];
        ulonglong2 wB = *(const ulonglong2*)&Wl4[k * 8 + og * 2 + 1];
        ull w2[4] = {wA.x, wA.y, wB.x, wB.y};
        float xa[4] = {xv.x, xv.y, xv.z, xv.w};
#pragma unroll
        for (int i = 0; i < 4; i++) {
            ull xd = pack2(xa[i], xa[i]);
#pragma unroll
            for (int jp = 0; jp < 4; jp++) ffma2(acc2[i][jp], xd, w2[jp]);
        }
    }
    __syncthreads();

    float* Ls = Xsf;
#pragma unroll
    for (int i = 0; i < 4; i++) {
        float2 p0 = unp(acc2[i][0]), p1 = unp(acc2[i][1]);
        float2 p2 = unp(acc2[i][2]), p3 = unp(acc2[i][3]);
        float* row = Ls + (4 * ng + i) * 33 + og * 8;
        row[0] = p0.x; row[1] = p0.y; row[2] = p1.x; row[3] = p1.y;
        row[4] = p2.x; row[5] = p2.y; row[6] = p3.x; row[7] = p3.y;
    }
    __syncthreads();

    int lane = t & 31;
    float wmn = 3.4e38f, wmx = 0.0f;
    for (int r = og; r < 128; r += 4) {
        int gn = n0 + r;
        float l = Ls[r * 33 + lane];
        float m = l;
#pragma unroll
        for (int off = 16; off; off >>= 1)
            m = fmaxf(m, __shfl_xor_sync(0xffffffffu, m, off));
        float p = expf(l - m);
        float sum = p;
#pragma unroll
        for (int off = 16; off; off >>= 1)
            sum += __shfl_xor_sync(0xffffffffu, sum, off);
        p /= sum;
        float term = -p * logf(p + 1e-9f);
#pragma unroll
        for (int off = 16; off; off >>= 1)
            term += __shfl_xor_sync(0xffffffffu, term, off);
        if (gn < n) {
            float wv = 1.0f / (term + 1e-10f);
            g_logits[(size_t)gn * 32 + lane] = l;
            if (lane == 0) {
                g_wts[gn] = wv;
                wmn = fminf(wmn, wv);
                wmx = fmaxf(wmx, wv);
            }
        }
    }
    if (lane == 0) {
        smm[og * 2]     = __float_as_int(wmn);
        smm[og * 2 + 1] = __float_as_int(wmx);
    }
    __syncthreads();
    if (t == 0) {
        int mn = smm[0], mx = smm[1];
#pragma unroll
        for (int i = 1; i < 4; i++) {
            mn = min(mn, smm[i * 2]);
            mx = max(mx, smm[i * 2 + 1]);
        }
        atomicMin(&g_mmint[0], mn);
        atomicMax(&g_mmint[1], mx);
    }
}

// ---------------- weighted sum ----------------
__global__ void wsum_k(int n) {
    __shared__ float sacc[8][33];
    int t = threadIdx.x, w = t >> 5, lane = t & 31;
    float mn = __int_as_float(g_mmint[0]);
    float den = __int_as_float(g_mmint[1]) - mn;
    float inv = den > 0.0f ? 1.0f / den : 0.0f;
    float acc = 0.0f, se = 0.0f;
    int warpG = blockIdx.x * 8 + w;
    int nwarp = gridDim.x * 8;
    for (int i = warpG; i < n; i += nwarp) {
        float e = expf((g_wts[i] - mn) * inv);
        acc += e * g_logits[(size_t)i * 32 + lane];
        se  += e;
    }
    sacc[w][lane] = acc;
    if (lane == 0) sacc[w][32] = se;
    __syncthreads();
    if (w == 0) {
        float a = sacc[0][lane];
#pragma unroll
        for (int r = 1; r < 8; r++) a += sacc[r][lane];
        atomicAdd(&g_acc[lane], a);
        if (lane == 0) {
            float b = sacc[0][32];
#pragma unroll
            for (int r = 1; r < 8; r++) b += sacc[r][32];
            atomicAdd(&g_acc[32], b);
        }
    }
}

// ---------------- final ----------------
__global__ void final_k(const float* __restrict__ w3,
                        const float* __restrict__ b3,
                        float* __restrict__ out) {
    int j = threadIdx.x;
    float invS = 1.0f / g_acc[32];
    float a = b3[j];
#pragma unroll
    for (int o = 0; o < 32; o++) a += (g_acc[o] * invS) * w3[o * 64 + j];
    out[j] = a;
}

// ---------------- launch ----------------
extern "C" void kernel_launch(void* const* d_in, const int* in_sizes, int n_in,
                              void* d_out, int out_size) {
    const float* x     = (const float*)d_in[0];
    const int*   ei    = (const int*)  d_in[1];
    const float* W1    = (const float*)d_in[2];
    const float* b1    = (const float*)d_in[3];
    const float* gamma = (const float*)d_in[4];
    const float* beta  = (const float*)d_in[5];
    const float* W2    = (const float*)d_in[6];
    const float* b2    = (const float*)d_in[7];
    const float* l2w   = (const float*)d_in[8];
    const float* l2b   = (const float*)d_in[9];
    const float* l3w   = (const float*)d_in[10];
    const float* l3b   = (const float*)d_in[11];
    float* out = (float*)d_out;

    int n = in_sizes[0] / 64;
    int e = in_sizes[1] / 2;
    const int* srcI = ei;
    const int* dstI = ei + e;

    int nb  = (n + 255) / 256;
    int eb  = (e + 255) / 256;
    int gb  = (n + 127) / 128;
    int gtb = (n * 16 + 255) / 256;
    int scb = (n + 2047) / 2048;

    deg_init_k <<<nb, 256>>>(n);
    deg_count_k<<<eb, 256>>>(dstI, e);
    scan1_k    <<<scb, 256>>>(n);
    scan2_k    <<<1, 32>>>(scb, n);
    scan3_k    <<<scb, 256>>>(n);
    fill_k     <<<eb, 256>>>(srcI, dstI, e);

    // layer 1
    gemm_fused_k<0><<<gb, 256>>>(x, W1, nullptr, nullptr, nullptr, n);
    gather_k       <<<gtb, 256>>>(0, n);

    // layer 2 (bias+BN+ReLU fused into loader)
    gemm_fused_k<1><<<gb, 256>>>(nullptr, W2, b1, gamma, beta, n);
    gather_k       <<<gtb, 256>>>(1, n);

    // readout
    logits_k  <<<gb, 128>>>(b2, l2w, l2b, n);
    wsum_k    <<<128, 256>>>(n);
    final_k   <<<1, 64>>>(l3w, l3b, out);
}

// round 9
// speedup vs baseline: 1.4810x; 1.0195x over previous
#include <cuda_runtime.h>
#include <cuda_fp16.h>

#define NMAX 100000
#define EMAX 1600000

typedef unsigned long long ull;

// ---------------- device scratch ----------------
__device__ float    g_deg   [NMAX];
__device__ float    g_dinv  [NMAX];
__device__ __half   g_tmp16 [NMAX * 64];   // h * dinv[src], fp16, 128 B/row
__device__ float    g_h1    [NMAX * 64];
__device__ float    g_h2    [NMAX * 64];
__device__ float    g_logits[NMAX * 32];
__device__ float    g_wts   [NMAX];
__device__ int      g_rowptr[NMAX + 1];    // BLOCK-LOCAL exclusive prefix (add g_boff[i>>11])
__device__ int      g_fill  [NMAX];
__device__ int      g_csrc  [EMAX];
__device__ int      g_bsum  [64];
__device__ int      g_boff  [64];
__device__ unsigned g_tctr  [4];           // dynamic tile counters (gemm0, gemm1, logits)
__device__ int      g_mmint [2];
__device__ float    g_acc   [33];

// ---------------- f32x2 packed helpers ----------------
__device__ __forceinline__ ull pack2(float a, float b) {
    ull r; unsigned ia = __float_as_uint(a), ib = __float_as_uint(b);
    asm("mov.b64 %0, {%1, %2};" : "=l"(r) : "r"(ia), "r"(ib));
    return r;
}
__device__ __forceinline__ void ffma2(ull& d, ull a, ull b) {
    asm("fma.rn.f32x2 %0, %1, %2, %0;" : "+l"(d) : "l"(a), "l"(b));
}
__device__ __forceinline__ void fadd2(ull& d, ull a) {
    asm("add.rn.f32x2 %0, %0, %1;" : "+l"(d) : "l"(a));
}
__device__ __forceinline__ float2 unp(ull v) {
    float2 r; unsigned lo = (unsigned)v, hi = (unsigned)(v >> 32);
    r.x = __uint_as_float(lo); r.y = __uint_as_float(hi);
    return r;
}
__device__ __forceinline__ ull cvt2(unsigned h2bits) {
    float2 f = __half22float2(*(__half2*)&h2bits);
    return pack2(f.x, f.y);
}

// ---------------- degree ----------------
__global__ void deg_init_k(int n) {
    int i = blockIdx.x * blockDim.x + threadIdx.x;
    if (i < n) g_deg[i] = 1.0f;   // self-loop
}
__global__ void deg_count_k(const int* __restrict__ dstI, int e) {
    int i = blockIdx.x * blockDim.x + threadIdx.x;
    if (i < e) atomicAdd(&g_deg[dstI[i]], 1.0f);
}

// ---------------- CSR rowptr scan (2 stages; offsets applied lazily) ----------------
__global__ void __launch_bounds__(256) scan1_k(int n) {
    __shared__ int wsum[8];
    int t = threadIdx.x;
    int base = blockIdx.x * 2048 + t * 8;
    int d[8]; int s = 0;
#pragma unroll
    for (int i = 0; i < 8; i++) {
        int idx = base + i;
        float dg = (idx < n) ? g_deg[idx] : 1.0f;
        if (idx < n) g_dinv[idx] = rsqrtf(dg);
        d[i] = (idx < n) ? (int)dg - 1 : 0;
        s += d[i];
    }
    int lane = t & 31, w = t >> 5;
    int inc = s;
#pragma unroll
    for (int off = 1; off < 32; off <<= 1) {
        int v = __shfl_up_sync(0xffffffffu, inc, off);
        if (lane >= off) inc += v;
    }
    if (lane == 31) wsum[w] = inc;
    __syncthreads();
    if (w == 0) {
        int v = (lane < 8) ? wsum[lane] : 0;
#pragma unroll
        for (int off = 1; off < 8; off <<= 1) {
            int u = __shfl_up_sync(0xffffffffu, v, off);
            if (lane >= off) v += u;
        }
        if (lane < 8) wsum[lane] = v;
    }
    __syncthreads();
    int exc = inc - s + (w > 0 ? wsum[w - 1] : 0);
#pragma unroll
    for (int i = 0; i < 8; i++) {
        int idx = base + i;
        if (idx < n) { g_rowptr[idx] = exc; g_fill[idx] = 0; }
        exc += d[i];
    }
    if (t == 255) g_bsum[blockIdx.x] = wsum[7];
}

// scan2: block offsets + local rowptr[n] + reset per-launch counters.
__global__ void scan2_k(int nb, int n) {
    int lane = threadIdx.x;
    int a = (lane      < nb) ? g_bsum[lane]      : 0;
    int b = (lane + 32 < nb) ? g_bsum[lane + 32] : 0;
    int ia = a, ib = b;
#pragma unroll
    for (int off = 1; off < 32; off <<= 1) {
        int v = __shfl_up_sync(0xffffffffu, ia, off);
        if (lane >= off) ia += v;
        int u = __shfl_up_sync(0xffffffffu, ib, off);
        if (lane >= off) ib += u;
    }
    int sumA = __shfl_sync(0xffffffffu, ia, 31);
    g_boff[lane]      = ia - a;            // exclusive offsets; entries >= nb hold total
    g_boff[lane + 32] = sumA + ib - b;
    if (lane == 0) {
        // local rowptr[n]: full local sum of last block (or 0 at block boundary)
        g_rowptr[n] = (n & 2047) ? g_bsum[n >> 11] : 0;
        g_mmint[0] = 0x7fffffff; g_mmint[1] = 0;
    }
    if (lane < 4) g_tctr[lane] = 0u;
    g_acc[lane] = 0.f;
    if (lane == 0) g_acc[32] = 0.f;
}

__global__ void fill_k(const int* __restrict__ srcI,
                       const int* __restrict__ dstI, int e) {
    int i = blockIdx.x * blockDim.x + threadIdx.x;
    if (i >= e) return;
    int s = __ldg(srcI + i);
    int d = __ldg(dstI + i);
    int pos = atomicAdd(&g_fill[d], 1);
    g_csrc[g_rowptr[d] + g_boff[d >> 11] + pos] = s;
}

// ---------------- persistent fused GEMM: dynamic 128-node tiles ----------------
// Epilogue writes h*dinv as fp16 (128 B/node). MODE selects input & counter.
template<int MODE>
__global__ void __launch_bounds__(256) gemm_fused_k(
    const float* __restrict__ Xin,
    const float* __restrict__ W,
    const float* __restrict__ b1,
    const float* __restrict__ gamma,
    const float* __restrict__ beta,
    int n, int ntiles)
{
    __shared__ float4 Xs4[64 * 32];
    __shared__ float4 Ws4[64 * 16];
    __shared__ unsigned sh_tile;
    const float* X = (MODE == 0) ? Xin : g_h1;
    int t = threadIdx.x;

    const float4* W4 = (const float4*)W;
    for (int i = t; i < 1024; i += 256) Ws4[i] = W4[i];

    const float rs = rsqrtf(1.0f + 1e-5f);
    float* Xsf = (float*)Xs4;

    for (;;) {
        __syncthreads();   // prev tile compute done; sh_tile consumed; Ws visible
        if (t == 0) sh_tile = atomicAdd(&g_tctr[MODE], 1u);
        __syncthreads();
        int tile = (int)sh_tile;
        if (tile >= ntiles) break;
        int n0 = tile * 128;

        for (int i = t; i < 2048; i += 256) {
            int node = i >> 4, c4 = i & 15;
            int gn = n0 + node;
            float4 v = make_float4(0.f, 0.f, 0.f, 0.f);
            if (gn < n) {
                v = ((const float4*)(X + (size_t)gn * 64))[c4];
                if (MODE == 1) {
                    float4 gm = ((const float4*)gamma)[c4];
                    float4 bt = ((const float4*)beta )[c4];
                    float4 bb = ((const float4*)b1   )[c4];
                    float a0 = rs * gm.x, a1 = rs * gm.y, a2 = rs * gm.z, a3 = rs * gm.w;
                    v.x = fmaxf(fmaf(v.x + bb.x, a0, bt.x), 0.f);
                    v.y = fmaxf(fmaf(v.y + bb.y, a1, bt.y), 0.f);
                    v.z = fmaxf(fmaf(v.z + bb.z, a2, bt.z), 0.f);
                    v.w = fmaxf(fmaf(v.w + bb.w, a3, bt.w), 0.f);
                }
            }
            int g = node >> 2, lo = node & 3;
            int sg = g ^ (c4 & 7);
            float* base = Xsf + (c4 * 4) * 128 + sg * 4 + lo;
            base[0]   = v.x;
            base[128] = v.y;
            base[256] = v.z;
            base[384] = v.w;
        }
        __syncthreads();

        int ng = t & 31;
        int og = t >> 5;
        ull acc2[4][4];
#pragma unroll
        for (int i = 0; i < 4; i++)
#pragma unroll
            for (int jp = 0; jp < 4; jp++) acc2[i][jp] = 0ull;

#pragma unroll 8
        for (int k = 0; k < 64; k++) {
            float4 xv = Xs4[k * 32 + (ng ^ ((k >> 2) & 7))];
            ulonglong2 wA = *(const ulonglong2*)&Ws4[k * 16 + og * 2];
            ulonglong2 wB = *(const ulonglong2*)&Ws4[k * 16 + og * 2 + 1];
            ull w2[4] = {wA.x, wA.y, wB.x, wB.y};
            float xa[4] = {xv.x, xv.y, xv.z, xv.w};
#pragma unroll
            for (int i = 0; i < 4; i++) {
                ull xd = pack2(xa[i], xa[i]);
#pragma unroll
                for (int jp = 0; jp < 4; jp++) ffma2(acc2[i][jp], xd, w2[jp]);
            }
        }

        int nb = n0 + 4 * ng;
        if (nb < n) {
            float4 dv = *(const float4*)(g_dinv + nb);
            float di[4] = {dv.x, dv.y, dv.z, dv.w};
#pragma unroll
            for (int i = 0; i < 4; i++) {
                int gn = nb + i;
                if (gn < n) {
                    float2 p0 = unp(acc2[i][0]), p1 = unp(acc2[i][1]);
                    float2 p2 = unp(acc2[i][2]), p3 = unp(acc2[i][3]);
                    float s = di[i];
                    __half2 h0 = __floats2half2_rn(p0.x * s, p0.y * s);
                    __half2 h1 = __floats2half2_rn(p1.x * s, p1.y * s);
                    __half2 h2 = __floats2half2_rn(p2.x * s, p2.y * s);
                    __half2 h3 = __floats2half2_rn(p3.x * s, p3.y * s);
                    uint4 pk;
                    pk.x = *(unsigned*)&h0; pk.y = *(unsigned*)&h1;
                    pk.z = *(unsigned*)&h2; pk.w = *(unsigned*)&h3;
                    *(uint4*)(g_tmp16 + (size_t)gn * 64 + og * 8) = pk;
                }
            }
        }
    }
}

// ---------------- CSR gather: out[d] = dinv[d] * sum tmp16[s] ----------------
__global__ void __launch_bounds__(256) gather_k(int which, int n) {
    int g = (blockIdx.x * blockDim.x + threadIdx.x) >> 4;
    int c = threadIdx.x & 15;
    if (g >= n) return;
    const uint2* T = (const uint2*)g_tmp16;
    ull a01, a23;
    {
        uint2 v = T[(size_t)g * 16 + c];      // self term
        a01 = cvt2(v.x);
        a23 = cvt2(v.y);
    }
    int j   = g_rowptr[g]     + g_boff[g >> 11];
    int end = g_rowptr[g + 1] + g_boff[(g + 1) >> 11];
    for (; j + 4 <= end; j += 4) {
        int s0 = __ldg(g_csrc + j);
        int s1 = __ldg(g_csrc + j + 1);
        int s2 = __ldg(g_csrc + j + 2);
        int s3 = __ldg(g_csrc + j + 3);
        uint2 v0 = T[(size_t)s0 * 16 + c];
        uint2 v1 = T[(size_t)s1 * 16 + c];
        uint2 v2 = T[(size_t)s2 * 16 + c];
        uint2 v3 = T[(size_t)s3 * 16 + c];
        fadd2(a01, cvt2(v0.x)); fadd2(a23, cvt2(v0.y));
        fadd2(a01, cvt2(v1.x)); fadd2(a23, cvt2(v1.y));
        fadd2(a01, cvt2(v2.x)); fadd2(a23, cvt2(v2.y));
        fadd2(a01, cvt2(v3.x)); fadd2(a23, cvt2(v3.y));
    }
    for (; j < end; j++) {
        int s0 = __ldg(g_csrc + j);
        uint2 v0 = T[(size_t)s0 * 16 + c];
        fadd2(a01, cvt2(v0.x)); fadd2(a23, cvt2(v0.y));
    }
    float dd = g_dinv[g];
    float2 r0 = unp(a01), r1 = unp(a23);
    float* outp = which ? g_h2 : g_h1;
    ((float4*)(outp + (size_t)g * 64))[c] =
        make_float4(r0.x * dd, r0.y * dd, r1.x * dd, r1.y * dd);
}

// ---------------- persistent logits + softmax + entropy + wts + min/max ----------------
__global__ void __launch_bounds__(128) logits_k(
    const float* __restrict__ b2,
    const float* __restrict__ W,    // [64,32] row-major
    const float* __restrict__ bb,   // [32]
    int n, int ntiles)
{
    __shared__ float4 Xs4[64 * 32];
    __shared__ float4 Wl4[64 * 8];
    __shared__ int smm[8];
    __shared__ unsigned sh_tile;
    int t = threadIdx.x;

    for (int i = t; i < 512; i += 128) Wl4[i] = ((const float4*)W)[i];
    float* Xsf = (float*)Xs4;

    for (;;) {
        __syncthreads();
        if (t == 0) sh_tile = atomicAdd(&g_tctr[2], 1u);
        __syncthreads();
        int tile = (int)sh_tile;
        if (tile >= ntiles) break;
        int n0 = tile * 128;

        for (int i = t; i < 2048; i += 128) {
            int node = i >> 4, c4 = i & 15;
            int gn = n0 + node;
            float4 v = make_float4(0.f, 0.f, 0.f, 0.f);
            if (gn < n) {
                v = ((const float4*)(g_h2 + (size_t)gn * 64))[c4];
                float4 b = ((const float4*)b2)[c4];
                v.x += b.x; v.y += b.y; v.z += b.z; v.w += b.w;
            }
            int g = node >> 2, lo = node & 3;
            int sg = g ^ (c4 & 7);
            float* base = Xsf + (c4 * 4) * 128 + sg * 4 + lo;
            base[0]   = v.x;
            base[128] = v.y;
            base[256] = v.z;
            base[384] = v.w;
        }
        __syncthreads();

        int ng = t & 31;
        int og = t >> 5;
        ull acc2[4][4];
        float4 bb0 = ((const float4*)bb)[og * 2];
        float4 bb1 = ((const float4*)bb)[og * 2 + 1];
        float bj[8] = {bb0.x, bb0.y, bb0.z, bb0.w, bb1.x, bb1.y, bb1.z, bb1.w};
#pragma unroll
        for (int i = 0; i < 4; i++)
#pragma unroll
            for (int jp = 0; jp < 4; jp++) acc2[i][jp] = pack2(bj[2 * jp], bj[2 * jp + 1]);

#pragma unroll 8
        for (int k = 0; k < 64; k++) {
            float4 xv = Xs4[k * 32 + (ng ^ ((k >> 2) & 7))];
            ulonglong2 wA = *(const ulonglong2*)&Wl4[k * 8 + og * 2];
            ulonglong2 wB = *(const ulonglong2*)&Wl4[k * 8 + og * 2 + 1];
            ull w2[4] = {wA.x, wA.y, wB.x, wB.y};
            float xa[4] = {xv.x, xv.y, xv.z, xv.w};
#pragma unroll
            for (int i = 0; i < 4; i++) {
                ull xd = pack2(xa[i], xa[i]);
#pragma unroll
                for (int jp = 0; jp < 4; jp++) ffma2(acc2[i][jp], xd, w2[jp]);
            }
        }
        __syncthreads();   // done reading Xs — reuse as Ls[128][33]

        float* Ls = Xsf;
#pragma unroll
        for (int i = 0; i < 4; i++) {
            float2 p0 = unp(acc2[i][0]), p1 = unp(acc2[i][1]);
            float2 p2 = unp(acc2[i][2]), p3 = unp(acc2[i][3]);
            float* row = Ls + (4 * ng + i) * 33 + og * 8;
            row[0] = p0.x; row[1] = p0.y; row[2] = p1.x; row[3] = p1.y;
            row[4] = p2.x; row[5] = p2.y; row[6] = p3.x; row[7] = p3.y;
        }
        __syncthreads();

        int lane = t & 31;
        float wmn = 3.4e38f, wmx = 0.0f;
        for (int r = og; r < 128; r += 4) {
            int gn = n0 + r;
            float l = Ls[r * 33 + lane];
            float m = l;
#pragma unroll
            for (int off = 16; off; off >>= 1)
                m = fmaxf(m, __shfl_xor_sync(0xffffffffu, m, off));
            float p = expf(l - m);
            float sum = p;
#pragma unroll
            for (int off = 16; off; off >>= 1)
                sum += __shfl_xor_sync(0xffffffffu, sum, off);
            p /= sum;
            float term = -p * logf(p + 1e-9f);
#pragma unroll
            for (int off = 16; off; off >>= 1)
                term += __shfl_xor_sync(0xffffffffu, term, off);
            if (gn < n) {
                float wv = 1.0f / (term + 1e-10f);
                g_logits[(size_t)gn * 32 + lane] = l;
                if (lane == 0) {
                    g_wts[gn] = wv;
                    wmn = fminf(wmn, wv);
                    wmx = fmaxf(wmx, wv);
                }
            }
        }
        if (lane == 0) {
            smm[og * 2]     = __float_as_int(wmn);
            smm[og * 2 + 1] = __float_as_int(wmx);
        }
        __syncthreads();
        if (t == 0) {
            int mn = smm[0], mx = smm[1];
#pragma unroll
            for (int i = 1; i < 4; i++) {
                mn = min(mn, smm[i * 2]);
                mx = max(mx, smm[i * 2 + 1]);
            }
            atomicMin(&g_mmint[0], mn);
            atomicMax(&g_mmint[1], mx);
        }
    }
}

// ---------------- weighted sum ----------------
__global__ void wsum_k(int n) {
    __shared__ float sacc[8][33];
    int t = threadIdx.x, w = t >> 5, lane = t & 31;
    float mn = __int_as_float(g_mmint[0]);
    float den = __int_as_float(g_mmint[1]) - mn;
    float inv = den > 0.0f ? 1.0f / den : 0.0f;
    float acc = 0.0f, se = 0.0f;
    int warpG = blockIdx.x * 8 + w;
    int nwarp = gridDim.x * 8;
    for (int i = warpG; i < n; i += nwarp) {
        float e = expf((g_wts[i] - mn) * inv);
        acc += e * g_logits[(size_t)i * 32 + lane];
        se  += e;
    }
    sacc[w][lane] = acc;
    if (lane == 0) sacc[w][32] = se;
    __syncthreads();
    if (w == 0) {
        float a = sacc[0][lane];
#pragma unroll
        for (int r = 1; r < 8; r++) a += sacc[r][lane];
        atomicAdd(&g_acc[lane], a);
        if (lane == 0) {
            float b = sacc[0][32];
#pragma unroll
            for (int r = 1; r < 8; r++) b += sacc[r][32];
            atomicAdd(&g_acc[32], b);
        }
    }
}

// ---------------- final ----------------
__global__ void final_k(const float* __restrict__ w3,
                        const float* __restrict__ b3,
                        float* __restrict__ out) {
    int j = threadIdx.x;
    float invS = 1.0f / g_acc[32];
    float a = b3[j];
#pragma unroll
    for (int o = 0; o < 32; o++) a += (g_acc[o] * invS) * w3[o * 64 + j];
    out[j] = a;
}

// ---------------- launch ----------------
extern "C" void kernel_launch(void* const* d_in, const int* in_sizes, int n_in,
                              void* d_out, int out_size) {
    const float* x     = (const float*)d_in[0];
    const int*   ei    = (const int*)  d_in[1];
    const float* W1    = (const float*)d_in[2];
    const float* b1    = (const float*)d_in[3];
    const float* gamma = (const float*)d_in[4];
    const float* beta  = (const float*)d_in[5];
    const float* W2    = (const float*)d_in[6];
    const float* b2    = (const float*)d_in[7];
    const float* l2w   = (const float*)d_in[8];
    const float* l2b   = (const float*)d_in[9];
    const float* l3w   = (const float*)d_in[10];
    const float* l3b   = (const float*)d_in[11];
    float* out = (float*)d_out;

    int n = in_sizes[0] / 64;
    int e = in_sizes[1] / 2;
    const int* srcI = ei;
    const int* dstI = ei + e;

    int nb     = (n + 255) / 256;
    int eb     = (e + 255) / 256;
    int ntiles = (n + 127) / 128;
    int gtb    = (n * 16 + 255) / 256;
    int scb    = (n + 2047) / 2048;

    deg_init_k <<<nb, 256>>>(n);
    deg_count_k<<<eb, 256>>>(dstI, e);
    scan1_k    <<<scb, 256>>>(n);
    scan2_k    <<<1, 32>>>(scb, n);
    fill_k     <<<eb, 256>>>(srcI, dstI, e);

    // layer 1 (persistent dynamic tiles; 3 blocks/SM RF-limited)
    gemm_fused_k<0><<<444, 256>>>(x, W1, nullptr, nullptr, nullptr, n, ntiles);
    gather_k       <<<gtb, 256>>>(0, n);

    // layer 2 (bias+BN+ReLU fused into loader)
    gemm_fused_k<1><<<444, 256>>>(nullptr, W2, b1, gamma, beta, n, ntiles);
    gather_k       <<<gtb, 256>>>(1, n);

    // readout
    logits_k  <<<740, 128>>>(b2, l2w, l2b, n, ntiles);
    wsum_k    <<<128, 256>>>(n);
    final_k   <<<1, 64>>>(l3w, l3b, out);
}

// round 10
// speedup vs baseline: 1.5003x; 1.0130x over previous
#include <cuda_runtime.h>
#include <cuda_fp16.h>

#define NMAX 100000
#define EMAX 1600000

typedef unsigned long long ull;

// ---------------- device scratch ----------------
__device__ float    g_deg   [NMAX];
__device__ float    g_dinv  [NMAX];
__device__ __half   g_tmp16 [NMAX * 64];   // h * dinv[src], fp16, 128 B/row
__device__ float    g_h1    [NMAX * 64];
__device__ float    g_h2    [NMAX * 64];
__device__ float    g_logits[NMAX * 32];
__device__ float    g_wts   [NMAX];
__device__ int      g_rowptr[NMAX + 1];    // BLOCK-LOCAL exclusive prefix (add g_boff[i>>11])
__device__ int      g_fill  [NMAX];
__device__ int      g_csrc  [EMAX];
__device__ int      g_bsum  [64];
__device__ int      g_boff  [64];
__device__ unsigned g_tctr  [4];           // dynamic tile counters + wsum ticket
__device__ unsigned g_done  = 0;           // scan1 last-block ticket
__device__ int      g_mmint [2];
__device__ float    g_acc   [33];

// ---------------- packed helpers ----------------
__device__ __forceinline__ ull pack2(float a, float b) {
    ull r; unsigned ia = __float_as_uint(a), ib = __float_as_uint(b);
    asm("mov.b64 %0, {%1, %2};" : "=l"(r) : "r"(ia), "r"(ib));
    return r;
}
__device__ __forceinline__ void ffma2(ull& d, ull a, ull b) {
    asm("fma.rn.f32x2 %0, %1, %2, %0;" : "+l"(d) : "l"(a), "l"(b));
}
__device__ __forceinline__ float2 unp(ull v) {
    float2 r; unsigned lo = (unsigned)v, hi = (unsigned)(v >> 32);
    r.x = __uint_as_float(lo); r.y = __uint_as_float(hi);
    return r;
}
__device__ __forceinline__ unsigned hadd2b(unsigned a, unsigned b) {
    unsigned r; asm("add.rn.f16x2 %0, %1, %2;" : "=r"(r) : "r"(a), "r"(b));
    return r;
}

// ---------------- degree ----------------
__global__ void deg_init_k(int n) {
    int i = blockIdx.x * blockDim.x + threadIdx.x;
    if (i < n) g_deg[i] = 1.0f;   // self-loop
}
__global__ void deg_count_k(const int* __restrict__ dstI, int e) {
    int i = blockIdx.x * blockDim.x + threadIdx.x;
    if (i < e) atomicAdd(&g_deg[dstI[i]], 1.0f);
}

// ---------------- CSR rowptr scan: single kernel (last block does stage 2) ----------------
__global__ void __launch_bounds__(256) scan1_k(int n) {
    __shared__ int wsum[8];
    __shared__ bool sLast;
    int t = threadIdx.x;
    int base = blockIdx.x * 2048 + t * 8;
    int d[8]; int s = 0;
#pragma unroll
    for (int i = 0; i < 8; i++) {
        int idx = base + i;
        float dg = (idx < n) ? g_deg[idx] : 1.0f;
        if (idx < n) g_dinv[idx] = rsqrtf(dg);
        d[i] = (idx < n) ? (int)dg - 1 : 0;
        s += d[i];
    }
    int lane = t & 31, w = t >> 5;
    int inc = s;
#pragma unroll
    for (int off = 1; off < 32; off <<= 1) {
        int v = __shfl_up_sync(0xffffffffu, inc, off);
        if (lane >= off) inc += v;
    }
    if (lane == 31) wsum[w] = inc;
    __syncthreads();
    if (w == 0) {
        int v = (lane < 8) ? wsum[lane] : 0;
#pragma unroll
        for (int off = 1; off < 8; off <<= 1) {
            int u = __shfl_up_sync(0xffffffffu, v, off);
            if (lane >= off) v += u;
        }
        if (lane < 8) wsum[lane] = v;
    }
    __syncthreads();
    int exc = inc - s + (w > 0 ? wsum[w - 1] : 0);
#pragma unroll
    for (int i = 0; i < 8; i++) {
        int idx = base + i;
        if (idx < n) { g_rowptr[idx] = exc; g_fill[idx] = 0; }
        exc += d[i];
    }
    // ticket: last block runs stage-2 scan over block sums
    if (t == 255) {
        g_bsum[blockIdx.x] = wsum[7];
        __threadfence();
        unsigned prev = atomicAdd(&g_done, 1u);
        sLast = (prev == gridDim.x - 1);
    }
    __syncthreads();
    if (sLast) {
        if (t == 0) g_done = 0;
        if (t < 32) {
            int nb = gridDim.x;
            int a = (lane      < nb) ? __ldcg(&g_bsum[lane])      : 0;
            int b = (lane + 32 < nb) ? __ldcg(&g_bsum[lane + 32]) : 0;
            int ia = a, ib = b;
#pragma unroll
            for (int off = 1; off < 32; off <<= 1) {
                int v = __shfl_up_sync(0xffffffffu, ia, off);
                if (lane >= off) ia += v;
                int u = __shfl_up_sync(0xffffffffu, ib, off);
                if (lane >= off) ib += u;
            }
            int sumA = __shfl_sync(0xffffffffu, ia, 31);
            g_boff[lane]      = ia - a;
            g_boff[lane + 32] = sumA + ib - b;
            if (lane == 0) {
                g_rowptr[n] = (n & 2047) ? __ldcg(&g_bsum[n >> 11]) : 0;
                g_mmint[0] = 0x7fffffff; g_mmint[1] = 0;
            }
            if (lane < 4) g_tctr[lane] = 0u;
            g_acc[lane] = 0.f;
            if (lane == 0) g_acc[32] = 0.f;
        }
    }
}

__global__ void fill_k(const int* __restrict__ srcI,
                       const int* __restrict__ dstI, int e) {
    int i = blockIdx.x * blockDim.x + threadIdx.x;
    if (i >= e) return;
    int s = __ldg(srcI + i);
    int d = __ldg(dstI + i);
    int pos = atomicAdd(&g_fill[d], 1);
    g_csrc[g_rowptr[d] + g_boff[d >> 11] + pos] = s;
}

// ---------------- persistent fused GEMM: dynamic 128-node tiles ----------------
template<int MODE>
__global__ void __launch_bounds__(256) gemm_fused_k(
    const float* __restrict__ Xin,
    const float* __restrict__ W,
    const float* __restrict__ b1,
    const float* __restrict__ gamma,
    const float* __restrict__ beta,
    int n, int ntiles)
{
    __shared__ float4 Xs4[64 * 32];
    __shared__ float4 Ws4[64 * 16];
    __shared__ unsigned sh_tile;
    const float* X = (MODE == 0) ? Xin : g_h1;
    int t = threadIdx.x;

    const float4* W4 = (const float4*)W;
    for (int i = t; i < 1024; i += 256) Ws4[i] = W4[i];

    const float rs = rsqrtf(1.0f + 1e-5f);
    float* Xsf = (float*)Xs4;

    for (;;) {
        __syncthreads();
        if (t == 0) sh_tile = atomicAdd(&g_tctr[MODE], 1u);
        __syncthreads();
        int tile = (int)sh_tile;
        if (tile >= ntiles) break;
        int n0 = tile * 128;

        for (int i = t; i < 2048; i += 256) {
            int node = i >> 4, c4 = i & 15;
            int gn = n0 + node;
            float4 v = make_float4(0.f, 0.f, 0.f, 0.f);
            if (gn < n) {
                v = ((const float4*)(X + (size_t)gn * 64))[c4];
                if (MODE == 1) {
                    float4 gm = ((const float4*)gamma)[c4];
                    float4 bt = ((const float4*)beta )[c4];
                    float4 bb = ((const float4*)b1   )[c4];
                    float a0 = rs * gm.x, a1 = rs * gm.y, a2 = rs * gm.z, a3 = rs * gm.w;
                    v.x = fmaxf(fmaf(v.x + bb.x, a0, bt.x), 0.f);
                    v.y = fmaxf(fmaf(v.y + bb.y, a1, bt.y), 0.f);
                    v.z = fmaxf(fmaf(v.z + bb.z, a2, bt.z), 0.f);
                    v.w = fmaxf(fmaf(v.w + bb.w, a3, bt.w), 0.f);
                }
            }
            int g = node >> 2, lo = node & 3;
            int sg = g ^ (c4 & 7);
            float* base = Xsf + (c4 * 4) * 128 + sg * 4 + lo;
            base[0]   = v.x;
            base[128] = v.y;
            base[256] = v.z;
            base[384] = v.w;
        }
        __syncthreads();

        int ng = t & 31;
        int og = t >> 5;
        ull acc2[4][4];
#pragma unroll
        for (int i = 0; i < 4; i++)
#pragma unroll
            for (int jp = 0; jp < 4; jp++) acc2[i][jp] = 0ull;

#pragma unroll 8
        for (int k = 0; k < 64; k++) {
            float4 xv = Xs4[k * 32 + (ng ^ ((k >> 2) & 7))];
            ulonglong2 wA = *(const ulonglong2*)&Ws4[k * 16 + og * 2];
            ulonglong2 wB = *(const ulonglong2*)&Ws4[k * 16 + og * 2 + 1];
            ull w2[4] = {wA.x, wA.y, wB.x, wB.y};
            float xa[4] = {xv.x, xv.y, xv.z, xv.w};
#pragma unroll
            for (int i = 0; i < 4; i++) {
                ull xd = pack2(xa[i], xa[i]);
#pragma unroll
                for (int jp = 0; jp < 4; jp++) ffma2(acc2[i][jp], xd, w2[jp]);
            }
        }

        int nb = n0 + 4 * ng;
        if (nb < n) {
            float4 dv = *(const float4*)(g_dinv + nb);
            float di[4] = {dv.x, dv.y, dv.z, dv.w};
#pragma unroll
            for (int i = 0; i < 4; i++) {
                int gn = nb + i;
                if (gn < n) {
                    float2 p0 = unp(acc2[i][0]), p1 = unp(acc2[i][1]);
                    float2 p2 = unp(acc2[i][2]), p3 = unp(acc2[i][3]);
                    float s = di[i];
                    __half2 h0 = __floats2half2_rn(p0.x * s, p0.y * s);
                    __half2 h1 = __floats2half2_rn(p1.x * s, p1.y * s);
                    __half2 h2 = __floats2half2_rn(p2.x * s, p2.y * s);
                    __half2 h3 = __floats2half2_rn(p3.x * s, p3.y * s);
                    uint4 pk;
                    pk.x = *(unsigned*)&h0; pk.y = *(unsigned*)&h1;
                    pk.z = *(unsigned*)&h2; pk.w = *(unsigned*)&h3;
                    *(uint4*)(g_tmp16 + (size_t)gn * 64 + og * 8) = pk;
                }
            }
        }
    }
}

// ---------------- CSR gather: fp16 HADD2 accumulation ----------------
__global__ void __launch_bounds__(256) gather_k(int which, int n) {
    int g = (blockIdx.x * blockDim.x + threadIdx.x) >> 4;
    int c = threadIdx.x & 15;
    if (g >= n) return;
    const uint2* T = (const uint2*)g_tmp16;
    uint2 self = T[(size_t)g * 16 + c];
    unsigned a0 = self.x, a1 = self.y;
    int j   = g_rowptr[g]     + g_boff[g >> 11];
    int end = g_rowptr[g + 1] + g_boff[(g + 1) >> 11];
    for (; j + 4 <= end; j += 4) {
        int s0 = __ldg(g_csrc + j);
        int s1 = __ldg(g_csrc + j + 1);
        int s2 = __ldg(g_csrc + j + 2);
        int s3 = __ldg(g_csrc + j + 3);
        uint2 v0 = T[(size_t)s0 * 16 + c];
        uint2 v1 = T[(size_t)s1 * 16 + c];
        uint2 v2 = T[(size_t)s2 * 16 + c];
        uint2 v3 = T[(size_t)s3 * 16 + c];
        a0 = hadd2b(a0, v0.x); a1 = hadd2b(a1, v0.y);
        a0 = hadd2b(a0, v1.x); a1 = hadd2b(a1, v1.y);
        a0 = hadd2b(a0, v2.x); a1 = hadd2b(a1, v2.y);
        a0 = hadd2b(a0, v3.x); a1 = hadd2b(a1, v3.y);
    }
    for (; j < end; j++) {
        int s0 = __ldg(g_csrc + j);
        uint2 v0 = T[(size_t)s0 * 16 + c];
        a0 = hadd2b(a0, v0.x); a1 = hadd2b(a1, v0.y);
    }
    float dd = g_dinv[g];
    float2 r0 = __half22float2(*(__half2*)&a0);
    float2 r1 = __half22float2(*(__half2*)&a1);
    float* outp = which ? g_h2 : g_h1;
    ((float4*)(outp + (size_t)g * 64))[c] =
        make_float4(r0.x * dd, r0.y * dd, r1.x * dd, r1.y * dd);
}

// ---------------- persistent logits + softmax + entropy + wts + min/max ----------------
__global__ void __launch_bounds__(128) logits_k(
    const float* __restrict__ b2,
    const float* __restrict__ W,    // [64,32] row-major
    const float* __restrict__ bb,   // [32]
    int n, int ntiles)
{
    __shared__ float4 Xs4[64 * 32];
    __shared__ float4 Wl4[64 * 8];
    __shared__ int smm[8];
    __shared__ unsigned sh_tile;
    int t = threadIdx.x;

    for (int i = t; i < 512; i += 128) Wl4[i] = ((const float4*)W)[i];
    float* Xsf = (float*)Xs4;

    for (;;) {
        __syncthreads();
        if (t == 0) sh_tile = atomicAdd(&g_tctr[2], 1u);
        __syncthreads();
        int tile = (int)sh_tile;
        if (tile >= ntiles) break;
        int n0 = tile * 128;

        for (int i = t; i < 2048; i += 128) {
            int node = i >> 4, c4 = i & 15;
            int gn = n0 + node;
            float4 v = make_float4(0.f, 0.f, 0.f, 0.f);
            if (gn < n) {
                v = ((const float4*)(g_h2 + (size_t)gn * 64))[c4];
                float4 b = ((const float4*)b2)[c4];
                v.x += b.x; v.y += b.y; v.z += b.z; v.w += b.w;
            }
            int g = node >> 2, lo = node & 3;
            int sg = g ^ (c4 & 7);
            float* base = Xsf + (c4 * 4) * 128 + sg * 4 + lo;
            base[0]   = v.x;
            base[128] = v.y;
            base[256] = v.z;
            base[384] = v.w;
        }
        __syncthreads();

        int ng = t & 31;
        int og = t >> 5;
        ull acc2[4][4];
        float4 bb0 = ((const float4*)bb)[og * 2];
        float4 bb1 = ((const float4*)bb)[og * 2 + 1];
        float bj[8] = {bb0.x, bb0.y, bb0.z, bb0.w, bb1.x, bb1.y, bb1.z, bb1.w};
#pragma unroll
        for (int i = 0; i < 4; i++)
#pragma unroll
            for (int jp = 0; jp < 4; jp++) acc2[i][jp] = pack2(bj[2 * jp], bj[2 * jp + 1]);

#pragma unroll 8
        for (int k = 0; k < 64; k++) {
            float4 xv = Xs4[k * 32 + (ng ^ ((k >> 2) & 7))];
            ulonglong2 wA = *(const ulonglong2*)&Wl4[k * 8 + og * 2];
            ulonglong2 wB = *(const ulonglong2*)&Wl4[k * 8 + og * 2 + 1];
            ull w2[4] = {wA.x, wA.y, wB.x, wB.y};
            float xa[4] = {xv.x, xv.y, xv.z, xv.w};
#pragma unroll
            for (int i = 0; i < 4; i++) {
                ull xd = pack2(xa[i], xa[i]);
#pragma unroll
                for (int jp = 0; jp < 4; jp++) ffma2(acc2[i][jp], xd, w2[jp]);
            }
        }
        __syncthreads();

        float* Ls = Xsf;
#pragma unroll
        for (int i = 0; i < 4; i++) {
            float2 p0 = unp(acc2[i][0]), p1 = unp(acc2[i][1]);
            float2 p2 = unp(acc2[i][2]), p3 = unp(acc2[i][3]);
            float* row = Ls + (4 * ng + i) * 33 + og * 8;
            row[0] = p0.x; row[1] = p0.y; row[2] = p1.x; row[3] = p1.y;
            row[4] = p2.x; row[5] = p2.y; row[6] = p3.x; row[7] = p3.y;
        }
        __syncthreads();

        int lane = t & 31;
        float wmn = 3.4e38f, wmx = 0.0f;
        for (int r = og; r < 128; r += 4) {
            int gn = n0 + r;
            float l = Ls[r * 33 + lane];
            float m = l;
#pragma unroll
            for (int off = 16; off; off >>= 1)
                m = fmaxf(m, __shfl_xor_sync(0xffffffffu, m, off));
            float p = expf(l - m);
            float sum = p;
#pragma unroll
            for (int off = 16; off; off >>= 1)
                sum += __shfl_xor_sync(0xffffffffu, sum, off);
            p /= sum;
            float term = -p * logf(p + 1e-9f);
#pragma unroll
            for (int off = 16; off; off >>= 1)
                term += __shfl_xor_sync(0xffffffffu, term, off);
            if (gn < n) {
                float wv = 1.0f / (term + 1e-10f);
                g_logits[(size_t)gn * 32 + lane] = l;
                if (lane == 0) {
                    g_wts[gn] = wv;
                    wmn = fminf(wmn, wv);
                    wmx = fmaxf(wmx, wv);
                }
            }
        }
        if (lane == 0) {
            smm[og * 2]     = __float_as_int(wmn);
            smm[og * 2 + 1] = __float_as_int(wmx);
        }
        __syncthreads();
        if (t == 0) {
            int mn = smm[0], mx = smm[1];
#pragma unroll
            for (int i = 1; i < 4; i++) {
                mn = min(mn, smm[i * 2]);
                mx = max(mx, smm[i * 2 + 1]);
            }
            atomicMin(&g_mmint[0], mn);
            atomicMax(&g_mmint[1], mx);
        }
    }
}

// ---------------- weighted sum + fused final matvec (last block) ----------------
__global__ void wsum_k(int n, const float* __restrict__ w3,
                       const float* __restrict__ b3, float* __restrict__ out) {
    __shared__ float sacc[8][33];
    __shared__ bool sl;
    int t = threadIdx.x, w = t >> 5, lane = t & 31;
    float mn = __int_as_float(g_mmint[0]);
    float den = __int_as_float(g_mmint[1]) - mn;
    float inv = den > 0.0f ? 1.0f / den : 0.0f;
    float acc = 0.0f, se = 0.0f;
    int warpG = blockIdx.x * 8 + w;
    int nwarp = gridDim.x * 8;
    for (int i = warpG; i < n; i += nwarp) {
        float e = expf((g_wts[i] - mn) * inv);
        acc += e * g_logits[(size_t)i * 32 + lane];
        se  += e;
    }
    sacc[w][lane] = acc;
    if (lane == 0) sacc[w][32] = se;
    __syncthreads();
    if (w == 0) {
        float a = sacc[0][lane];
#pragma unroll
        for (int r = 1; r < 8; r++) a += sacc[r][lane];
        atomicAdd(&g_acc[lane], a);
        if (lane == 0) {
            float b = sacc[0][32];
#pragma unroll
            for (int r = 1; r < 8; r++) b += sacc[r][32];
            atomicAdd(&g_acc[32], b);
        }
        __threadfence();
    }
    __syncthreads();
    if (t == 0) {
        unsigned prev = atomicAdd(&g_tctr[3], 1u);
        sl = (prev == gridDim.x - 1);
    }
    __syncthreads();
    if (sl && t < 64) {
        float invS = 1.0f / __ldcg(&g_acc[32]);
        float a = b3[t];
#pragma unroll
        for (int o = 0; o < 32; o++)
            a += (__ldcg(&g_acc[o]) * invS) * w3[o * 64 + t];
        out[t] = a;
    }
}

// ---------------- launch ----------------
extern "C" void kernel_launch(void* const* d_in, const int* in_sizes, int n_in,
                              void* d_out, int out_size) {
    const float* x     = (const float*)d_in[0];
    const int*   ei    = (const int*)  d_in[1];
    const float* W1    = (const float*)d_in[2];
    const float* b1    = (const float*)d_in[3];
    const float* gamma = (const float*)d_in[4];
    const float* beta  = (const float*)d_in[5];
    const float* W2    = (const float*)d_in[6];
    const float* b2    = (const float*)d_in[7];
    const float* l2w   = (const float*)d_in[8];
    const float* l2b   = (const float*)d_in[9];
    const float* l3w   = (const float*)d_in[10];
    const float* l3b   = (const float*)d_in[11];
    float* out = (float*)d_out;

    int n = in_sizes[0] / 64;
    int e = in_sizes[1] / 2;
    const int* srcI = ei;
    const int* dstI = ei + e;

    int nb     = (n + 255) / 256;
    int eb     = (e + 255) / 256;
    int ntiles = (n + 127) / 128;
    int gtb    = (n * 16 + 255) / 256;
    int scb    = (n + 2047) / 2048;

    // side stream + fork/join events (created per call; graph capture safe)
    cudaStream_t s2;
    cudaEvent_t evA, evB;
    cudaStreamCreateWithFlags(&s2, cudaStreamNonBlocking);
    cudaEventCreateWithFlags(&evA, cudaEventDisableTiming);
    cudaEventCreateWithFlags(&evB, cudaEventDisableTiming);

    deg_init_k <<<nb, 256>>>(n);
    deg_count_k<<<eb, 256>>>(dstI, e);
    scan1_k    <<<scb, 256>>>(n);   // includes stage-2 scan + counter resets

    // fork: fill on s2, overlapped with layer-1 GEMM on main stream
    cudaEventRecord(evA, 0);
    cudaStreamWaitEvent(s2, evA, 0);
    fill_k<<<eb, 256, 0, s2>>>(srcI, dstI, e);
    cudaEventRecord(evB, s2);

    gemm_fused_k<0><<<444, 256>>>(x, W1, nullptr, nullptr, nullptr, n, ntiles);
    cudaStreamWaitEvent(0, evB, 0);   // join before gather needs g_csrc

    gather_k<<<gtb, 256>>>(0, n);

    gemm_fused_k<1><<<444, 256>>>(nullptr, W2, b1, gamma, beta, n, ntiles);
    gather_k   <<<gtb, 256>>>(1, n);

    logits_k<<<740, 128>>>(b2, l2w, l2b, n, ntiles);
    wsum_k  <<<128, 256>>>(n, l3w, l3b, out);   // includes final matvec
}